// round 4
// baseline (speedup 1.0000x reference)
#include <cuda_runtime.h>
#include <math.h>

#define NU 50000
#define NI 30000
#define NN 80000
#define DD 64

#define NNZ_UI 1000000
#define NNZ_R  800000
#define NNZ_II 300000

// ---------------- scratch (static device globals) -----------------------------
__device__ float g_cat1[NN * DD];
__device__ float g_cat2[NN * DD];
__device__ float g_img_ui[NN * DD];
__device__ float g_txt_ui[NN * DD];
__device__ float g_gi0[NI * DD];
__device__ float g_gi1[NI * DD];
__device__ float g_gt0[NI * DD];
__device__ float g_gt1[NI * DD];

__device__ __forceinline__ float lrelu(float x) { return x >= 0.f ? x : 0.01f * x; }

__device__ __forceinline__ void red4(float* dst, float v, float4 x) {
    asm volatile("red.global.add.v4.f32 [%0], {%1, %2, %3, %4};"
                 :: "l"(dst), "f"(v * x.x), "f"(v * x.y), "f"(v * x.z), "f"(v * x.w)
                 : "memory");
}

// ---------------- ui hop1: gathers from virtual concat [item;user] ------------
__global__ void spmm_cat_kernel(const int* __restrict__ rows, const int* __restrict__ cols,
                                const float* __restrict__ vals,
                                const float* __restrict__ item_emb,
                                const float* __restrict__ user_emb,
                                float* __restrict__ out, int nnz) {
    int t = blockIdx.x * blockDim.x + threadIdx.x;
    int j = t & 15;
    int e0 = (t >> 4) * 2;
    if (e0 >= nnz) return;

    int c0 = __ldg(&cols[e0]);
    int c1 = __ldg(&cols[e0 + 1]);
    const float4* p0 = (c0 < NI)
        ? reinterpret_cast<const float4*>(item_emb) + (size_t)c0 * 16
        : reinterpret_cast<const float4*>(user_emb) + (size_t)(c0 - NI) * 16;
    const float4* p1 = (c1 < NI)
        ? reinterpret_cast<const float4*>(item_emb) + (size_t)c1 * 16
        : reinterpret_cast<const float4*>(user_emb) + (size_t)(c1 - NI) * 16;
    float4 x0 = __ldg(p0 + j);
    float4 x1 = __ldg(p1 + j);
    int   r0 = __ldg(&rows[e0]);
    int   r1 = __ldg(&rows[e0 + 1]);
    float v0 = __ldg(&vals[e0]);
    float v1 = __ldg(&vals[e0 + 1]);
    red4(out + (size_t)r0 * 64 + j * 4, v0, x0);
    red4(out + (size_t)r1 * 64 + j * 4, v1, x1);
}

// ---------------- generic spmm: out[rows[e]] += vals[e]*x[cols[e]] ------------
__global__ void spmm2_kernel(const int* __restrict__ rows, const int* __restrict__ cols,
                             const float* __restrict__ vals, const float* __restrict__ x,
                             float* __restrict__ out, int nnz) {
    int t = blockIdx.x * blockDim.x + threadIdx.x;
    int j = t & 15;
    int e0 = (t >> 4) * 2;
    if (e0 >= nnz) return;

    int c0 = __ldg(&cols[e0]);
    int c1 = __ldg(&cols[e0 + 1]);
    float4 x0 = __ldg(reinterpret_cast<const float4*>(x) + (size_t)c0 * 16 + j);
    float4 x1 = __ldg(reinterpret_cast<const float4*>(x) + (size_t)c1 * 16 + j);
    int   r0 = __ldg(&rows[e0]);
    int   r1 = __ldg(&rows[e0 + 1]);
    float v0 = __ldg(&vals[e0]);
    float v1 = __ldg(&vals[e0 + 1]);
    red4(out + (size_t)r0 * 64 + j * 4, v0, x0);
    red4(out + (size_t)r1 * 64 + j * 4, v1, x1);
}

// ---------------- dual spmm over one edge list (R): both modalities -----------
__global__ void spmm_dualR_kernel(const int* __restrict__ rows, const int* __restrict__ cols,
                                  const float* __restrict__ vals,
                                  const float* __restrict__ xi, const float* __restrict__ xt,
                                  float* __restrict__ oi, float* __restrict__ ot, int nnz) {
    int t = blockIdx.x * blockDim.x + threadIdx.x;
    int j = t & 15;
    int e = t >> 4;
    if (e >= nnz) return;

    int   c = __ldg(&cols[e]);
    int   r = __ldg(&rows[e]);
    float v = __ldg(&vals[e]);
    float4 a = __ldg(reinterpret_cast<const float4*>(xi) + (size_t)c * 16 + j);
    float4 b = __ldg(reinterpret_cast<const float4*>(xt) + (size_t)c * 16 + j);
    red4(oi + (size_t)r * 64 + j * 4, v, a);
    red4(ot + (size_t)r * 64 + j * 4, v, b);
}

// ---------------- mean of [cat0(virtual), cat1, cat2] -> out[0] ----------------
__global__ void mean3_cat_kernel(const float* __restrict__ item_emb,
                                 const float* __restrict__ user_emb,
                                 const float* __restrict__ b, const float* __restrict__ c,
                                 float* __restrict__ out) {
    int i = blockIdx.x * blockDim.x + threadIdx.x;
    const int NI4 = NI * 16, NN4 = NN * 16;
    if (i >= NN4) return;
    float4 A = (i < NI4) ? __ldg(reinterpret_cast<const float4*>(item_emb) + i)
                         : __ldg(reinterpret_cast<const float4*>(user_emb) + (i - NI4));
    float4 B = reinterpret_cast<const float4*>(b)[i];
    float4 C = reinterpret_cast<const float4*>(c)[i];
    const float s = 1.f / 3.f;
    reinterpret_cast<float4*>(out)[i] =
        make_float4((A.x + B.x + C.x) * s, (A.y + B.y + C.y) * s,
                    (A.z + B.z + C.z) * s, (A.w + B.w + C.w) * s);
}

// ---------------- fused projection + BN + lrelu + gate -------------------------
// gated[r,d] = item_emb[r,d] * sigmoid( feat[r,:] @ Wg[:,d] + bg[d] )
// feat[r,d]  = lrelu( (x[r,:] @ W[:,d] + b[d]) * g[d]/sqrt(1+eps) + beta[d] )
template <int F>
__global__ void projgate_kernel(const float* __restrict__ x, const float* __restrict__ W,
                                const float* __restrict__ b, const float* __restrict__ g,
                                const float* __restrict__ beta,
                                const float* __restrict__ Wg, const float* __restrict__ bg,
                                const float* __restrict__ item_emb,
                                float* __restrict__ out) {
    __shared__ float  sX[32][68];
    __shared__ float4 sW[64][16];
    __shared__ float  sF[32][68];

    int tid = threadIdx.x;
    int cg  = tid & 7;
    int row = tid >> 3;
    int r0  = blockIdx.x * 32;
    int r   = r0 + row;

    float acc[8];
#pragma unroll
    for (int i = 0; i < 8; i++) acc[i] = 0.f;

    for (int kc = 0; kc < F; kc += 64) {
        {
            int lc = cg * 8;
            float4 a = make_float4(0.f, 0.f, 0.f, 0.f), bb = a;
            if (r < NI) {
                const float* src = x + (size_t)r * F + kc + lc;
                a  = *reinterpret_cast<const float4*>(src);
                bb = *reinterpret_cast<const float4*>(src + 4);
            }
            *reinterpret_cast<float4*>(&sX[row][lc])     = a;
            *reinterpret_cast<float4*>(&sX[row][lc + 4]) = bb;
        }
#pragma unroll
        for (int i = 0; i < 4; i++) {
            int idx = tid + i * 256;
            int wk  = idx >> 4;
            int wc  = idx & 15;
            sW[wk][wc] = *reinterpret_cast<const float4*>(&W[(size_t)(kc + wk) * 64 + wc * 4]);
        }
        __syncthreads();

#pragma unroll
        for (int k = 0; k < 64; k++) {
            float  xv = sX[row][k];
            float4 w0 = sW[k][cg * 2];
            float4 w1 = sW[k][cg * 2 + 1];
            acc[0] += xv * w0.x; acc[1] += xv * w0.y; acc[2] += xv * w0.z; acc[3] += xv * w0.w;
            acc[4] += xv * w1.x; acc[5] += xv * w1.y; acc[6] += xv * w1.z; acc[7] += xv * w1.w;
        }
        __syncthreads();
    }

    // feat for this (row, 8 cols) -> sF
    {
        const float rs = rsqrtf(1.f + 1e-5f);
        int dbase = cg * 8;
#pragma unroll
        for (int jj = 0; jj < 8; jj++) {
            int d = dbase + jj;
            float v = acc[jj] + __ldg(&b[d]);
            v = v * (__ldg(&g[d]) * rs) + __ldg(&beta[d]);
            sF[row][dbase + jj] = lrelu(v);
        }
    }
    // stage Wg into sW (all mainloop reads done: trailing __syncthreads above)
#pragma unroll
    for (int i = 0; i < 4; i++) {
        int idx = tid + i * 256;
        int wk  = idx >> 4;
        int wc  = idx & 15;
        sW[wk][wc] = *reinterpret_cast<const float4*>(&Wg[(size_t)wk * 64 + wc * 4]);
    }
    __syncthreads();

    float gacc[8];
    {
        int dbase = cg * 8;
#pragma unroll
        for (int jj = 0; jj < 8; jj++) gacc[jj] = __ldg(&bg[dbase + jj]);
    }
#pragma unroll
    for (int k = 0; k < 64; k++) {
        float  fv = sF[row][k];
        float4 w0 = sW[k][cg * 2];
        float4 w1 = sW[k][cg * 2 + 1];
        gacc[0] += fv * w0.x; gacc[1] += fv * w0.y; gacc[2] += fv * w0.z; gacc[3] += fv * w0.w;
        gacc[4] += fv * w1.x; gacc[5] += fv * w1.y; gacc[6] += fv * w1.z; gacc[7] += fv * w1.w;
    }

    if (r < NI) {
        int dbase = cg * 8;
#pragma unroll
        for (int jj = 0; jj < 8; jj++) {
            int d = dbase + jj;
            float sig = 1.f / (1.f + __expf(-gacc[jj]));
            out[(size_t)r * 64 + d] = item_emb[(size_t)r * 64 + d] * sig;
        }
    }
}

// ---------------- attention fusion (writes out[1..3]) -------------------------
__global__ __launch_bounds__(256, 2)
void att_kernel(const float* __restrict__ img_ui, const float* __restrict__ txt_ui,
                const float* __restrict__ W1, const float* __restrict__ b1,
                const float* __restrict__ w2, float* __restrict__ out) {
    __shared__ float sei[4][64], set_[4][64];
    __shared__ float wsum[8][2];
    int d    = threadIdx.x & 63;
    int sub  = threadIdx.x >> 6;
    int warp = threadIdx.x >> 5;
    int lane = threadIdx.x & 31;

    float Wc[64];
#pragma unroll
    for (int k = 0; k < 64; k++) Wc[k] = __ldg(&W1[k * 64 + d]);
    float b1d = __ldg(&b1[d]);
    float w2d = __ldg(&w2[d]);

    int r0 = blockIdx.x * 128;
#pragma unroll 1
    for (int i = 0; i < 32; i++) {
        int r = r0 + i * 4 + sub;
        size_t base = (size_t)r * 64 + d;
        float ei = __ldg(&img_ui[base]);
        float et = __ldg(&txt_ui[base]);
        sei[sub][d]  = ei;
        set_[sub][d] = et;
        __syncthreads();

        float hi = b1d, ht = b1d;
#pragma unroll
        for (int k = 0; k < 64; k += 4) {
            float4 a = *reinterpret_cast<const float4*>(&sei[sub][k]);
            float4 b = *reinterpret_cast<const float4*>(&set_[sub][k]);
            hi += a.x * Wc[k] + a.y * Wc[k + 1] + a.z * Wc[k + 2] + a.w * Wc[k + 3];
            ht += b.x * Wc[k] + b.y * Wc[k + 1] + b.z * Wc[k + 2] + b.w * Wc[k + 3];
        }
        hi = lrelu(hi) * w2d;
        ht = lrelu(ht) * w2d;
#pragma unroll
        for (int o = 16; o; o >>= 1) {
            hi += __shfl_xor_sync(0xffffffffu, hi, o);
            ht += __shfl_xor_sync(0xffffffffu, ht, o);
        }
        if (lane == 0) { wsum[warp][0] = hi; wsum[warp][1] = ht; }
        __syncthreads();
        int wbase = sub * 2;
        float si = wsum[wbase][0] + wsum[wbase + 1][0];
        float st = wsum[wbase][1] + wsum[wbase + 1][1];
        float wimg = 1.f / (1.f + __expf(st - si));
        float common = wimg * ei + (1.f - wimg) * et;

        out[(size_t)1 * NN * DD + base] = ei - common;
        out[(size_t)2 * NN * DD + base] = et - common;
        out[(size_t)3 * NN * DD + base] = common;
        __syncthreads();
    }
}

// ---------------- driver ------------------------------------------------------
static inline int g256(long long n) { return (int)((n + 255) / 256); }

extern "C" void kernel_launch(void* const* d_in, const int* in_sizes, int n_in,
                              void* d_out, int out_size) {
    const float* user_emb  = (const float*)d_in[0];
    const float* item_emb  = (const float*)d_in[1];
    const float* image_emb = (const float*)d_in[2];
    const float* text_emb  = (const float*)d_in[3];
    const float* W_img = (const float*)d_in[4];
    const float* b_img = (const float*)d_in[5];
    const float* bng_img = (const float*)d_in[6];
    const float* bnb_img = (const float*)d_in[7];
    const float* W_txt = (const float*)d_in[8];
    const float* b_txt = (const float*)d_in[9];
    const float* bng_txt = (const float*)d_in[10];
    const float* bnb_txt = (const float*)d_in[11];
    const float* W_gi = (const float*)d_in[12];
    const float* b_gi = (const float*)d_in[13];
    const float* W_gt = (const float*)d_in[14];
    const float* b_gt = (const float*)d_in[15];
    const float* W_c1 = (const float*)d_in[16];
    const float* b_c1 = (const float*)d_in[17];
    const float* w_c2 = (const float*)d_in[18];
    const float* ui_vals = (const float*)d_in[19];
    const float* R_vals  = (const float*)d_in[20];
    const float* ii_i_vals = (const float*)d_in[21];
    const float* ii_t_vals = (const float*)d_in[22];
    const int* ui_rows = (const int*)d_in[23];
    const int* ui_cols = (const int*)d_in[24];
    const int* R_rows  = (const int*)d_in[25];
    const int* R_cols  = (const int*)d_in[26];
    const int* ii_i_rows = (const int*)d_in[27];
    const int* ii_i_cols = (const int*)d_in[28];
    const int* ii_t_rows = (const int*)d_in[29];
    const int* ii_t_cols = (const int*)d_in[30];

    float* out = (float*)d_out;

    void* p;
    cudaGetSymbolAddress(&p, g_cat1);   float* cat1   = (float*)p;
    cudaGetSymbolAddress(&p, g_cat2);   float* cat2   = (float*)p;
    cudaGetSymbolAddress(&p, g_img_ui); float* img_ui = (float*)p;
    cudaGetSymbolAddress(&p, g_txt_ui); float* txt_ui = (float*)p;
    cudaGetSymbolAddress(&p, g_gi0);    float* gi0    = (float*)p;
    cudaGetSymbolAddress(&p, g_gi1);    float* gi1    = (float*)p;
    cudaGetSymbolAddress(&p, g_gt0);    float* gt0    = (float*)p;
    cudaGetSymbolAddress(&p, g_gt1);    float* gt1    = (float*)p;

    float* img_items = img_ui + (size_t)NU * DD;
    float* txt_items = txt_ui + (size_t)NU * DD;

    static cudaStream_t sA = nullptr, sB = nullptr, sC = nullptr;
    static cudaEvent_t eFork = nullptr, eA = nullptr, eB = nullptr, eC = nullptr;
    if (!sA) {
        cudaStreamCreateWithFlags(&sA, cudaStreamNonBlocking);
        cudaStreamCreateWithFlags(&sB, cudaStreamNonBlocking);
        cudaStreamCreateWithFlags(&sC, cudaStreamNonBlocking);
        cudaEventCreateWithFlags(&eFork, cudaEventDisableTiming);
        cudaEventCreateWithFlags(&eA, cudaEventDisableTiming);
        cudaEventCreateWithFlags(&eB, cudaEventDisableTiming);
        cudaEventCreateWithFlags(&eC, cudaEventDisableTiming);
    }

    const int G_UI = NNZ_UI / 32;          // 31250
    const int G_II = NNZ_II / 32;          //  9375
    const int G_R  = NNZ_R * 16 / 256;     // 50000
    const size_t NNB = (size_t)NN * DD * sizeof(float);
    const size_t NIB = (size_t)NI * DD * sizeof(float);

    // fork from capture stream
    cudaEventRecord(eFork, 0);
    cudaStreamWaitEvent(sA, eFork, 0);
    cudaStreamWaitEvent(sB, eFork, 0);
    cudaStreamWaitEvent(sC, eFork, 0);

    // chain A: ui GCN -> out[0]
    cudaMemsetAsync(cat1, 0, NNB, sA);
    cudaMemsetAsync(cat2, 0, NNB, sA);
    spmm_cat_kernel<<<G_UI, 256, 0, sA>>>(ui_rows, ui_cols, ui_vals, item_emb, user_emb, cat1, NNZ_UI);
    spmm2_kernel<<<G_UI, 256, 0, sA>>>(ui_rows, ui_cols, ui_vals, cat1, cat2, NNZ_UI);
    mean3_cat_kernel<<<g256((long long)NN * 16), 256, 0, sA>>>(item_emb, user_emb, cat1, cat2, out);
    cudaEventRecord(eA, sA);

    // chain B: image branch
    cudaMemsetAsync(img_ui, 0, NNB, sB);
    cudaMemsetAsync(gi1, 0, NIB, sB);
    projgate_kernel<512><<<(NI + 31) / 32, 256, 0, sB>>>(image_emb, W_img, b_img, bng_img, bnb_img,
                                                         W_gi, b_gi, item_emb, gi0);
    spmm2_kernel<<<G_II, 256, 0, sB>>>(ii_i_rows, ii_i_cols, ii_i_vals, gi0, gi1, NNZ_II);
    spmm2_kernel<<<G_II, 256, 0, sB>>>(ii_i_rows, ii_i_cols, ii_i_vals, gi1, img_items, NNZ_II);

    // chain C: text branch
    cudaMemsetAsync(txt_ui, 0, NNB, sC);
    cudaMemsetAsync(gt1, 0, NIB, sC);
    projgate_kernel<384><<<(NI + 31) / 32, 256, 0, sC>>>(text_emb, W_txt, b_txt, bng_txt, bnb_txt,
                                                         W_gt, b_gt, item_emb, gt0);
    spmm2_kernel<<<G_II, 256, 0, sC>>>(ii_t_rows, ii_t_cols, ii_t_vals, gt0, gt1, NNZ_II);
    spmm2_kernel<<<G_II, 256, 0, sC>>>(ii_t_rows, ii_t_cols, ii_t_vals, gt1, txt_items, NNZ_II);
    cudaEventRecord(eC, sC);

    // join C into B, run dual-R (one edge pass, both modalities)
    cudaStreamWaitEvent(sB, eC, 0);
    spmm_dualR_kernel<<<G_R, 256, 0, sB>>>(R_rows, R_cols, R_vals, img_items, txt_items,
                                           img_ui, txt_ui, NNZ_R);
    cudaEventRecord(eB, sB);

    // join A,B -> att on capture stream
    cudaStreamWaitEvent(0, eA, 0);
    cudaStreamWaitEvent(0, eB, 0);
    att_kernel<<<NN / 128, 256>>>(img_ui, txt_ui, W_c1, b_c1, w_c2, out);
}

// round 5
// speedup vs baseline: 1.5372x; 1.5372x over previous
#include <cuda_runtime.h>
#include <math.h>

#define NU 50000
#define NI 30000
#define NN 80000
#define DD 64

#define NNZ_UI 1000000
#define NNZ_R  800000
#define NNZ_II 300000

// ---------------- scratch (static device globals) -----------------------------
__device__ float g_cat1[NN * DD];
__device__ float g_cat2[NN * DD];
__device__ float g_img_ui[NN * DD];
__device__ float g_txt_ui[NN * DD];
__device__ float g_gi0[NI * DD];
__device__ float g_gi1[NI * DD];
__device__ float g_gt0[NI * DD];
__device__ float g_gt1[NI * DD];

__device__ __forceinline__ float lrelu(float x) { return x >= 0.f ? x : 0.01f * x; }

__device__ __forceinline__ void red4(float* dst, float v, float4 x) {
    asm volatile("red.global.add.v4.f32 [%0], {%1, %2, %3, %4};"
                 :: "l"(dst), "f"(v * x.x), "f"(v * x.y), "f"(v * x.z), "f"(v * x.w)
                 : "memory");
}

// ---------------- ui hop1: gathers from virtual concat [item;user] ------------
__global__ void spmm_cat_kernel(const int* __restrict__ rows, const int* __restrict__ cols,
                                const float* __restrict__ vals,
                                const float* __restrict__ item_emb,
                                const float* __restrict__ user_emb,
                                float* __restrict__ out, int nnz) {
    int t = blockIdx.x * blockDim.x + threadIdx.x;
    int j = t & 15;
    int e0 = (t >> 4) * 2;
    if (e0 >= nnz) return;

    int c0 = __ldg(&cols[e0]);
    int c1 = __ldg(&cols[e0 + 1]);
    const float4* p0 = (c0 < NI)
        ? reinterpret_cast<const float4*>(item_emb) + (size_t)c0 * 16
        : reinterpret_cast<const float4*>(user_emb) + (size_t)(c0 - NI) * 16;
    const float4* p1 = (c1 < NI)
        ? reinterpret_cast<const float4*>(item_emb) + (size_t)c1 * 16
        : reinterpret_cast<const float4*>(user_emb) + (size_t)(c1 - NI) * 16;
    float4 x0 = __ldg(p0 + j);
    float4 x1 = __ldg(p1 + j);
    int   r0 = __ldg(&rows[e0]);
    int   r1 = __ldg(&rows[e0 + 1]);
    float v0 = __ldg(&vals[e0]);
    float v1 = __ldg(&vals[e0 + 1]);
    red4(out + (size_t)r0 * 64 + j * 4, v0, x0);
    red4(out + (size_t)r1 * 64 + j * 4, v1, x1);
}

// ---------------- generic spmm: out[rows[e]] += vals[e]*x[cols[e]] ------------
__global__ void spmm2_kernel(const int* __restrict__ rows, const int* __restrict__ cols,
                             const float* __restrict__ vals, const float* __restrict__ x,
                             float* __restrict__ out, int nnz) {
    int t = blockIdx.x * blockDim.x + threadIdx.x;
    int j = t & 15;
    int e0 = (t >> 4) * 2;
    if (e0 >= nnz) return;

    int c0 = __ldg(&cols[e0]);
    int c1 = __ldg(&cols[e0 + 1]);
    float4 x0 = __ldg(reinterpret_cast<const float4*>(x) + (size_t)c0 * 16 + j);
    float4 x1 = __ldg(reinterpret_cast<const float4*>(x) + (size_t)c1 * 16 + j);
    int   r0 = __ldg(&rows[e0]);
    int   r1 = __ldg(&rows[e0 + 1]);
    float v0 = __ldg(&vals[e0]);
    float v1 = __ldg(&vals[e0 + 1]);
    red4(out + (size_t)r0 * 64 + j * 4, v0, x0);
    red4(out + (size_t)r1 * 64 + j * 4, v1, x1);
}

// ---------------- dual spmm over one edge list (R): both modalities -----------
__global__ void spmm_dualR_kernel(const int* __restrict__ rows, const int* __restrict__ cols,
                                  const float* __restrict__ vals,
                                  const float* __restrict__ xi, const float* __restrict__ xt,
                                  float* __restrict__ oi, float* __restrict__ ot, int nnz) {
    int t = blockIdx.x * blockDim.x + threadIdx.x;
    int j = t & 15;
    int e = t >> 4;
    if (e >= nnz) return;

    int   c = __ldg(&cols[e]);
    int   r = __ldg(&rows[e]);
    float v = __ldg(&vals[e]);
    float4 a = __ldg(reinterpret_cast<const float4*>(xi) + (size_t)c * 16 + j);
    float4 b = __ldg(reinterpret_cast<const float4*>(xt) + (size_t)c * 16 + j);
    red4(oi + (size_t)r * 64 + j * 4, v, a);
    red4(ot + (size_t)r * 64 + j * 4, v, b);
}

// ---------------- mean of [cat0(virtual), cat1, cat2] -> out[0] ----------------
__global__ void mean3_cat_kernel(const float* __restrict__ item_emb,
                                 const float* __restrict__ user_emb,
                                 const float* __restrict__ b, const float* __restrict__ c,
                                 float* __restrict__ out) {
    int i = blockIdx.x * blockDim.x + threadIdx.x;
    const int NI4 = NI * 16, NN4 = NN * 16;
    if (i >= NN4) return;
    float4 A = (i < NI4) ? __ldg(reinterpret_cast<const float4*>(item_emb) + i)
                         : __ldg(reinterpret_cast<const float4*>(user_emb) + (i - NI4));
    float4 B = reinterpret_cast<const float4*>(b)[i];
    float4 C = reinterpret_cast<const float4*>(c)[i];
    const float s = 1.f / 3.f;
    reinterpret_cast<float4*>(out)[i] =
        make_float4((A.x + B.x + C.x) * s, (A.y + B.y + C.y) * s,
                    (A.z + B.z + C.z) * s, (A.w + B.w + C.w) * s);
}

// ---------------- fused projection + BN + lrelu + gate -------------------------
// Register-blocked: 256 threads compute a 128x64 tile; each thread 4 rows x 8 cols.
template <int F>
__global__ __launch_bounds__(256)
void projgate_kernel(const float* __restrict__ x, const float* __restrict__ W,
                     const float* __restrict__ b, const float* __restrict__ g,
                     const float* __restrict__ beta,
                     const float* __restrict__ Wg, const float* __restrict__ bg,
                     const float* __restrict__ item_emb,
                     float* __restrict__ out) {
    __shared__ float sX[128 * 68];      // X tile (pitch 68); overlaid as feat after main loop
    __shared__ float sWs[64 * 64];      // W k-tile / Wg

    const int tid = threadIdx.x;
    const int cg  = tid & 7;            // col group: cols cg*8 .. cg*8+7
    const int rq  = tid >> 3;           // 0..31 ; rows rq, rq+32, rq+64, rq+96
    const int r0  = blockIdx.x * 128;
    const int dbase = cg * 8;

    float a0[8], a1[8], a2[8], a3[8];
#pragma unroll
    for (int i = 0; i < 8; i++) { a0[i] = 0.f; a1[i] = 0.f; a2[i] = 0.f; a3[i] = 0.f; }

    for (int kc = 0; kc < F; kc += 64) {
        // stage X tile: 128 rows x 64 k
        {
            int lr = tid >> 1, half = tid & 1;
            int gr = r0 + lr;
            float4* dst = reinterpret_cast<float4*>(&sX[lr * 68 + half * 32]);
            if (gr < NI) {
                const float4* src = reinterpret_cast<const float4*>(x + (size_t)gr * F + kc) + half * 8;
#pragma unroll
                for (int j = 0; j < 8; j++) dst[j] = __ldg(src + j);
            } else {
#pragma unroll
                for (int j = 0; j < 8; j++) dst[j] = make_float4(0.f, 0.f, 0.f, 0.f);
            }
        }
        // stage W tile: 64 k x 64 cols
#pragma unroll
        for (int i = 0; i < 4; i++) {
            int idx = tid + i * 256;
            int wk = idx >> 4, wc = idx & 15;
            reinterpret_cast<float4*>(&sWs[wk * 64])[wc] =
                __ldg(reinterpret_cast<const float4*>(&W[(size_t)(kc + wk) * 64]) + wc);
        }
        __syncthreads();

#pragma unroll
        for (int k = 0; k < 64; k++) {
            float x0 = sX[rq * 68 + k];
            float x1 = sX[(rq + 32) * 68 + k];
            float x2 = sX[(rq + 64) * 68 + k];
            float x3 = sX[(rq + 96) * 68 + k];
            float4 w0 = *reinterpret_cast<const float4*>(&sWs[k * 64 + dbase]);
            float4 w1 = *reinterpret_cast<const float4*>(&sWs[k * 64 + dbase + 4]);
            a0[0] += x0 * w0.x; a0[1] += x0 * w0.y; a0[2] += x0 * w0.z; a0[3] += x0 * w0.w;
            a0[4] += x0 * w1.x; a0[5] += x0 * w1.y; a0[6] += x0 * w1.z; a0[7] += x0 * w1.w;
            a1[0] += x1 * w0.x; a1[1] += x1 * w0.y; a1[2] += x1 * w0.z; a1[3] += x1 * w0.w;
            a1[4] += x1 * w1.x; a1[5] += x1 * w1.y; a1[6] += x1 * w1.z; a1[7] += x1 * w1.w;
            a2[0] += x2 * w0.x; a2[1] += x2 * w0.y; a2[2] += x2 * w0.z; a2[3] += x2 * w0.w;
            a2[4] += x2 * w1.x; a2[5] += x2 * w1.y; a2[6] += x2 * w1.z; a2[7] += x2 * w1.w;
            a3[0] += x3 * w0.x; a3[1] += x3 * w0.y; a3[2] += x3 * w0.z; a3[3] += x3 * w0.w;
            a3[4] += x3 * w1.x; a3[5] += x3 * w1.y; a3[6] += x3 * w1.z; a3[7] += x3 * w1.w;
        }
        __syncthreads();
    }

    // BN + lrelu -> feat (overlay sX); then gate GEMM from feat
    {
        const float rs = rsqrtf(1.f + 1e-5f);
        float bv[8], gv[8], bev[8];
#pragma unroll
        for (int j = 0; j < 8; j++) {
            int d = dbase + j;
            bv[j]  = __ldg(&b[d]);
            gv[j]  = __ldg(&g[d]) * rs;
            bev[j] = __ldg(&beta[d]);
        }
#pragma unroll
        for (int q = 0; q < 4; q++) {
            float* acc = (q == 0) ? a0 : (q == 1) ? a1 : (q == 2) ? a2 : a3;
            int rr = rq + q * 32;
            float4 f0, f1;
            f0.x = lrelu((acc[0] + bv[0]) * gv[0] + bev[0]);
            f0.y = lrelu((acc[1] + bv[1]) * gv[1] + bev[1]);
            f0.z = lrelu((acc[2] + bv[2]) * gv[2] + bev[2]);
            f0.w = lrelu((acc[3] + bv[3]) * gv[3] + bev[3]);
            f1.x = lrelu((acc[4] + bv[4]) * gv[4] + bev[4]);
            f1.y = lrelu((acc[5] + bv[5]) * gv[5] + bev[5]);
            f1.z = lrelu((acc[6] + bv[6]) * gv[6] + bev[6]);
            f1.w = lrelu((acc[7] + bv[7]) * gv[7] + bev[7]);
            *reinterpret_cast<float4*>(&sX[rr * 68 + dbase])     = f0;
            *reinterpret_cast<float4*>(&sX[rr * 68 + dbase + 4]) = f1;
        }
    }
    // stage Wg
#pragma unroll
    for (int i = 0; i < 4; i++) {
        int idx = tid + i * 256;
        int wk = idx >> 4, wc = idx & 15;
        reinterpret_cast<float4*>(&sWs[wk * 64])[wc] =
            __ldg(reinterpret_cast<const float4*>(&Wg[(size_t)wk * 64]) + wc);
    }
    __syncthreads();

    // gate GEMM: reuse accumulators
#pragma unroll
    for (int j = 0; j < 8; j++) {
        float bgv = __ldg(&bg[dbase + j]);
        a0[j] = bgv; a1[j] = bgv; a2[j] = bgv; a3[j] = bgv;
    }
#pragma unroll
    for (int k = 0; k < 64; k++) {
        float x0 = sX[rq * 68 + k];
        float x1 = sX[(rq + 32) * 68 + k];
        float x2 = sX[(rq + 64) * 68 + k];
        float x3 = sX[(rq + 96) * 68 + k];
        float4 w0 = *reinterpret_cast<const float4*>(&sWs[k * 64 + dbase]);
        float4 w1 = *reinterpret_cast<const float4*>(&sWs[k * 64 + dbase + 4]);
        a0[0] += x0 * w0.x; a0[1] += x0 * w0.y; a0[2] += x0 * w0.z; a0[3] += x0 * w0.w;
        a0[4] += x0 * w1.x; a0[5] += x0 * w1.y; a0[6] += x0 * w1.z; a0[7] += x0 * w1.w;
        a1[0] += x1 * w0.x; a1[1] += x1 * w0.y; a1[2] += x1 * w0.z; a1[3] += x1 * w0.w;
        a1[4] += x1 * w1.x; a1[5] += x1 * w1.y; a1[6] += x1 * w1.z; a1[7] += x1 * w1.w;
        a2[0] += x2 * w0.x; a2[1] += x2 * w0.y; a2[2] += x2 * w0.z; a2[3] += x2 * w0.w;
        a2[4] += x2 * w1.x; a2[5] += x2 * w1.y; a2[6] += x2 * w1.z; a2[7] += x2 * w1.w;
        a3[0] += x3 * w0.x; a3[1] += x3 * w0.y; a3[2] += x3 * w0.z; a3[3] += x3 * w0.w;
        a3[4] += x3 * w1.x; a3[5] += x3 * w1.y; a3[6] += x3 * w1.z; a3[7] += x3 * w1.w;
    }

    // sigmoid gate * item_emb -> out
#pragma unroll
    for (int q = 0; q < 4; q++) {
        float* acc = (q == 0) ? a0 : (q == 1) ? a1 : (q == 2) ? a2 : a3;
        int gr = r0 + rq + q * 32;
        if (gr < NI) {
            const float4* it = reinterpret_cast<const float4*>(item_emb + (size_t)gr * 64 + dbase);
            float4 i0 = __ldg(it), i1 = __ldg(it + 1);
            float4 o0, o1;
            o0.x = i0.x / (1.f + __expf(-acc[0]));
            o0.y = i0.y / (1.f + __expf(-acc[1]));
            o0.z = i0.z / (1.f + __expf(-acc[2]));
            o0.w = i0.w / (1.f + __expf(-acc[3]));
            o1.x = i1.x / (1.f + __expf(-acc[4]));
            o1.y = i1.y / (1.f + __expf(-acc[5]));
            o1.z = i1.z / (1.f + __expf(-acc[6]));
            o1.w = i1.w / (1.f + __expf(-acc[7]));
            float4* dst = reinterpret_cast<float4*>(out + (size_t)gr * 64 + dbase);
            dst[0] = o0; dst[1] = o1;
        }
    }
}

// ---------------- attention fusion (writes out[1..3]) -------------------------
__global__ __launch_bounds__(256, 2)
void att_kernel(const float* __restrict__ img_ui, const float* __restrict__ txt_ui,
                const float* __restrict__ W1, const float* __restrict__ b1,
                const float* __restrict__ w2, float* __restrict__ out) {
    __shared__ float sei[4][64], set_[4][64];
    __shared__ float wsum[8][2];
    int d    = threadIdx.x & 63;
    int sub  = threadIdx.x >> 6;
    int warp = threadIdx.x >> 5;
    int lane = threadIdx.x & 31;

    float Wc[64];
#pragma unroll
    for (int k = 0; k < 64; k++) Wc[k] = __ldg(&W1[k * 64 + d]);
    float b1d = __ldg(&b1[d]);
    float w2d = __ldg(&w2[d]);

    int r0 = blockIdx.x * 128;
#pragma unroll 1
    for (int i = 0; i < 32; i++) {
        int r = r0 + i * 4 + sub;
        size_t base = (size_t)r * 64 + d;
        float ei = __ldg(&img_ui[base]);
        float et = __ldg(&txt_ui[base]);
        sei[sub][d]  = ei;
        set_[sub][d] = et;
        __syncthreads();

        float hi = b1d, ht = b1d;
#pragma unroll
        for (int k = 0; k < 64; k += 4) {
            float4 a = *reinterpret_cast<const float4*>(&sei[sub][k]);
            float4 b = *reinterpret_cast<const float4*>(&set_[sub][k]);
            hi += a.x * Wc[k] + a.y * Wc[k + 1] + a.z * Wc[k + 2] + a.w * Wc[k + 3];
            ht += b.x * Wc[k] + b.y * Wc[k + 1] + b.z * Wc[k + 2] + b.w * Wc[k + 3];
        }
        hi = lrelu(hi) * w2d;
        ht = lrelu(ht) * w2d;
#pragma unroll
        for (int o = 16; o; o >>= 1) {
            hi += __shfl_xor_sync(0xffffffffu, hi, o);
            ht += __shfl_xor_sync(0xffffffffu, ht, o);
        }
        if (lane == 0) { wsum[warp][0] = hi; wsum[warp][1] = ht; }
        __syncthreads();
        int wbase = sub * 2;
        float si = wsum[wbase][0] + wsum[wbase + 1][0];
        float st = wsum[wbase][1] + wsum[wbase + 1][1];
        float wimg = 1.f / (1.f + __expf(st - si));
        float common = wimg * ei + (1.f - wimg) * et;

        out[(size_t)1 * NN * DD + base] = ei - common;
        out[(size_t)2 * NN * DD + base] = et - common;
        out[(size_t)3 * NN * DD + base] = common;
        __syncthreads();
    }
}

// ---------------- driver ------------------------------------------------------
static inline int g256(long long n) { return (int)((n + 255) / 256); }

extern "C" void kernel_launch(void* const* d_in, const int* in_sizes, int n_in,
                              void* d_out, int out_size) {
    const float* user_emb  = (const float*)d_in[0];
    const float* item_emb  = (const float*)d_in[1];
    const float* image_emb = (const float*)d_in[2];
    const float* text_emb  = (const float*)d_in[3];
    const float* W_img = (const float*)d_in[4];
    const float* b_img = (const float*)d_in[5];
    const float* bng_img = (const float*)d_in[6];
    const float* bnb_img = (const float*)d_in[7];
    const float* W_txt = (const float*)d_in[8];
    const float* b_txt = (const float*)d_in[9];
    const float* bng_txt = (const float*)d_in[10];
    const float* bnb_txt = (const float*)d_in[11];
    const float* W_gi = (const float*)d_in[12];
    const float* b_gi = (const float*)d_in[13];
    const float* W_gt = (const float*)d_in[14];
    const float* b_gt = (const float*)d_in[15];
    const float* W_c1 = (const float*)d_in[16];
    const float* b_c1 = (const float*)d_in[17];
    const float* w_c2 = (const float*)d_in[18];
    const float* ui_vals = (const float*)d_in[19];
    const float* R_vals  = (const float*)d_in[20];
    const float* ii_i_vals = (const float*)d_in[21];
    const float* ii_t_vals = (const float*)d_in[22];
    const int* ui_rows = (const int*)d_in[23];
    const int* ui_cols = (const int*)d_in[24];
    const int* R_rows  = (const int*)d_in[25];
    const int* R_cols  = (const int*)d_in[26];
    const int* ii_i_rows = (const int*)d_in[27];
    const int* ii_i_cols = (const int*)d_in[28];
    const int* ii_t_rows = (const int*)d_in[29];
    const int* ii_t_cols = (const int*)d_in[30];

    float* out = (float*)d_out;

    void* p;
    cudaGetSymbolAddress(&p, g_cat1);   float* cat1   = (float*)p;
    cudaGetSymbolAddress(&p, g_cat2);   float* cat2   = (float*)p;
    cudaGetSymbolAddress(&p, g_img_ui); float* img_ui = (float*)p;
    cudaGetSymbolAddress(&p, g_txt_ui); float* txt_ui = (float*)p;
    cudaGetSymbolAddress(&p, g_gi0);    float* gi0    = (float*)p;
    cudaGetSymbolAddress(&p, g_gi1);    float* gi1    = (float*)p;
    cudaGetSymbolAddress(&p, g_gt0);    float* gt0    = (float*)p;
    cudaGetSymbolAddress(&p, g_gt1);    float* gt1    = (float*)p;

    float* img_items = img_ui + (size_t)NU * DD;
    float* txt_items = txt_ui + (size_t)NU * DD;

    static cudaStream_t sA = nullptr, sB = nullptr, sC = nullptr;
    static cudaEvent_t eFork = nullptr, eA = nullptr, eB = nullptr, eC = nullptr;
    if (!sA) {
        cudaStreamCreateWithFlags(&sA, cudaStreamNonBlocking);
        cudaStreamCreateWithFlags(&sB, cudaStreamNonBlocking);
        cudaStreamCreateWithFlags(&sC, cudaStreamNonBlocking);
        cudaEventCreateWithFlags(&eFork, cudaEventDisableTiming);
        cudaEventCreateWithFlags(&eA, cudaEventDisableTiming);
        cudaEventCreateWithFlags(&eB, cudaEventDisableTiming);
        cudaEventCreateWithFlags(&eC, cudaEventDisableTiming);
    }

    const int G_UI = NNZ_UI / 32;          // 31250
    const int G_II = NNZ_II / 32;          //  9375
    const int G_R  = NNZ_R * 16 / 256;     // 50000
    const size_t NNB = (size_t)NN * DD * sizeof(float);
    const size_t NIB = (size_t)NI * DD * sizeof(float);

    // fork from capture stream
    cudaEventRecord(eFork, 0);
    cudaStreamWaitEvent(sA, eFork, 0);
    cudaStreamWaitEvent(sB, eFork, 0);
    cudaStreamWaitEvent(sC, eFork, 0);

    // chain A: ui GCN -> out[0]
    cudaMemsetAsync(cat1, 0, NNB, sA);
    cudaMemsetAsync(cat2, 0, NNB, sA);
    spmm_cat_kernel<<<G_UI, 256, 0, sA>>>(ui_rows, ui_cols, ui_vals, item_emb, user_emb, cat1, NNZ_UI);
    spmm2_kernel<<<G_UI, 256, 0, sA>>>(ui_rows, ui_cols, ui_vals, cat1, cat2, NNZ_UI);
    mean3_cat_kernel<<<g256((long long)NN * 16), 256, 0, sA>>>(item_emb, user_emb, cat1, cat2, out);
    cudaEventRecord(eA, sA);

    // chain B: image branch
    cudaMemsetAsync(img_ui, 0, NNB, sB);
    cudaMemsetAsync(gi1, 0, NIB, sB);
    projgate_kernel<512><<<(NI + 127) / 128, 256, 0, sB>>>(image_emb, W_img, b_img, bng_img, bnb_img,
                                                           W_gi, b_gi, item_emb, gi0);
    spmm2_kernel<<<G_II, 256, 0, sB>>>(ii_i_rows, ii_i_cols, ii_i_vals, gi0, gi1, NNZ_II);
    spmm2_kernel<<<G_II, 256, 0, sB>>>(ii_i_rows, ii_i_cols, ii_i_vals, gi1, img_items, NNZ_II);

    // chain C: text branch
    cudaMemsetAsync(txt_ui, 0, NNB, sC);
    cudaMemsetAsync(gt1, 0, NIB, sC);
    projgate_kernel<384><<<(NI + 127) / 128, 256, 0, sC>>>(text_emb, W_txt, b_txt, bng_txt, bnb_txt,
                                                           W_gt, b_gt, item_emb, gt0);
    spmm2_kernel<<<G_II, 256, 0, sC>>>(ii_t_rows, ii_t_cols, ii_t_vals, gt0, gt1, NNZ_II);
    spmm2_kernel<<<G_II, 256, 0, sC>>>(ii_t_rows, ii_t_cols, ii_t_vals, gt1, txt_items, NNZ_II);
    cudaEventRecord(eC, sC);

    // join C into B, run dual-R (one edge pass, both modalities)
    cudaStreamWaitEvent(sB, eC, 0);
    spmm_dualR_kernel<<<G_R, 256, 0, sB>>>(R_rows, R_cols, R_vals, img_items, txt_items,
                                           img_ui, txt_ui, NNZ_R);
    cudaEventRecord(eB, sB);

    // join A,B -> att on capture stream
    cudaStreamWaitEvent(0, eA, 0);
    cudaStreamWaitEvent(0, eB, 0);
    att_kernel<<<NN / 128, 256>>>(img_ui, txt_ui, W_c1, b_c1, w_c2, out);
}

// round 6
// speedup vs baseline: 1.5711x; 1.0220x over previous
#include <cuda_runtime.h>
#include <math.h>

#define NU 50000
#define NI 30000
#define NN 80000
#define DD 64

#define NNZ_UI 1000000
#define NNZ_R  800000
#define NNZ_II 300000

// ---------------- scratch (static device globals) -----------------------------
__device__ float g_cat1[NN * DD];
__device__ float g_cat2[NN * DD];
__device__ float g_img_ui[NN * DD];
__device__ float g_txt_ui[NN * DD];
__device__ float g_gi0[NI * DD];
__device__ float g_gi1[NI * DD];
__device__ float g_gt0[NI * DD];
__device__ float g_gt1[NI * DD];

__device__ __forceinline__ float lrelu(float x) { return x >= 0.f ? x : 0.01f * x; }

__device__ __forceinline__ void red4(float* dst, float v, float4 x) {
    asm volatile("red.global.add.v4.f32 [%0], {%1, %2, %3, %4};"
                 :: "l"(dst), "f"(v * x.x), "f"(v * x.y), "f"(v * x.z), "f"(v * x.w)
                 : "memory");
}

// ---------------- ui hop1: gathers from virtual concat [item;user] ------------
__global__ void spmm_cat_kernel(const int* __restrict__ rows, const int* __restrict__ cols,
                                const float* __restrict__ vals,
                                const float* __restrict__ item_emb,
                                const float* __restrict__ user_emb,
                                float* __restrict__ out, int nnz) {
    int t = blockIdx.x * blockDim.x + threadIdx.x;
    int j = t & 15;
    int e0 = (t >> 4) * 2;
    if (e0 >= nnz) return;

    int c0 = __ldg(&cols[e0]);
    int c1 = __ldg(&cols[e0 + 1]);
    const float4* p0 = (c0 < NI)
        ? reinterpret_cast<const float4*>(item_emb) + (size_t)c0 * 16
        : reinterpret_cast<const float4*>(user_emb) + (size_t)(c0 - NI) * 16;
    const float4* p1 = (c1 < NI)
        ? reinterpret_cast<const float4*>(item_emb) + (size_t)c1 * 16
        : reinterpret_cast<const float4*>(user_emb) + (size_t)(c1 - NI) * 16;
    float4 x0 = __ldg(p0 + j);
    float4 x1 = __ldg(p1 + j);
    int   r0 = __ldg(&rows[e0]);
    int   r1 = __ldg(&rows[e0 + 1]);
    float v0 = __ldg(&vals[e0]);
    float v1 = __ldg(&vals[e0 + 1]);
    red4(out + (size_t)r0 * 64 + j * 4, v0, x0);
    red4(out + (size_t)r1 * 64 + j * 4, v1, x1);
}

// ---------------- generic spmm: out[rows[e]] += vals[e]*x[cols[e]] ------------
__global__ void spmm2_kernel(const int* __restrict__ rows, const int* __restrict__ cols,
                             const float* __restrict__ vals, const float* __restrict__ x,
                             float* __restrict__ out, int nnz) {
    int t = blockIdx.x * blockDim.x + threadIdx.x;
    int j = t & 15;
    int e0 = (t >> 4) * 2;
    if (e0 >= nnz) return;

    int c0 = __ldg(&cols[e0]);
    int c1 = __ldg(&cols[e0 + 1]);
    float4 x0 = __ldg(reinterpret_cast<const float4*>(x) + (size_t)c0 * 16 + j);
    float4 x1 = __ldg(reinterpret_cast<const float4*>(x) + (size_t)c1 * 16 + j);
    int   r0 = __ldg(&rows[e0]);
    int   r1 = __ldg(&rows[e0 + 1]);
    float v0 = __ldg(&vals[e0]);
    float v1 = __ldg(&vals[e0 + 1]);
    red4(out + (size_t)r0 * 64 + j * 4, v0, x0);
    red4(out + (size_t)r1 * 64 + j * 4, v1, x1);
}

// ---------------- dual spmm over one edge list (R): both modalities -----------
__global__ void spmm_dualR_kernel(const int* __restrict__ rows, const int* __restrict__ cols,
                                  const float* __restrict__ vals,
                                  const float* __restrict__ xi, const float* __restrict__ xt,
                                  float* __restrict__ oi, float* __restrict__ ot, int nnz) {
    int t = blockIdx.x * blockDim.x + threadIdx.x;
    int j = t & 15;
    int e = t >> 4;
    if (e >= nnz) return;

    int   c = __ldg(&cols[e]);
    int   r = __ldg(&rows[e]);
    float v = __ldg(&vals[e]);
    float4 a = __ldg(reinterpret_cast<const float4*>(xi) + (size_t)c * 16 + j);
    float4 b = __ldg(reinterpret_cast<const float4*>(xt) + (size_t)c * 16 + j);
    red4(oi + (size_t)r * 64 + j * 4, v, a);
    red4(ot + (size_t)r * 64 + j * 4, v, b);
}

// ---------------- mean of [cat0(virtual), cat1, cat2] -> out[0] ----------------
__global__ void mean3_cat_kernel(const float* __restrict__ item_emb,
                                 const float* __restrict__ user_emb,
                                 const float* __restrict__ b, const float* __restrict__ c,
                                 float* __restrict__ out) {
    int i = blockIdx.x * blockDim.x + threadIdx.x;
    const int NI4 = NI * 16, NN4 = NN * 16;
    if (i >= NN4) return;
    float4 A = (i < NI4) ? __ldg(reinterpret_cast<const float4*>(item_emb) + i)
                         : __ldg(reinterpret_cast<const float4*>(user_emb) + (i - NI4));
    float4 B = reinterpret_cast<const float4*>(b)[i];
    float4 C = reinterpret_cast<const float4*>(c)[i];
    const float s = 1.f / 3.f;
    reinterpret_cast<float4*>(out)[i] =
        make_float4((A.x + B.x + C.x) * s, (A.y + B.y + C.y) * s,
                    (A.z + B.z + C.z) * s, (A.w + B.w + C.w) * s);
}

// ---------------- fused projection + BN + lrelu + gate -------------------------
// Register-blocked 128x64 tile; k-chunked float4 X loads from smem.
template <int F>
__global__ __launch_bounds__(256)
void projgate_kernel(const float* __restrict__ x, const float* __restrict__ W,
                     const float* __restrict__ b, const float* __restrict__ g,
                     const float* __restrict__ beta,
                     const float* __restrict__ Wg, const float* __restrict__ bg,
                     const float* __restrict__ item_emb,
                     float* __restrict__ out) {
    __shared__ float sX[128 * 68];      // X tile (pitch 68, 16B-aligned rows); feat overlay
    __shared__ float sWs[64 * 64];      // W k-tile / Wg

    const int tid = threadIdx.x;
    const int cg  = tid & 7;
    const int rq  = tid >> 3;           // rows rq, rq+32, rq+64, rq+96
    const int r0  = blockIdx.x * 128;
    const int dbase = cg * 8;

    float a0[8], a1[8], a2[8], a3[8];
#pragma unroll
    for (int i = 0; i < 8; i++) { a0[i] = 0.f; a1[i] = 0.f; a2[i] = 0.f; a3[i] = 0.f; }

    for (int kc = 0; kc < F; kc += 64) {
        {
            int lr = tid >> 1, half = tid & 1;
            int gr = r0 + lr;
            float4* dst = reinterpret_cast<float4*>(&sX[lr * 68 + half * 32]);
            if (gr < NI) {
                const float4* src = reinterpret_cast<const float4*>(x + (size_t)gr * F + kc) + half * 8;
#pragma unroll
                for (int j = 0; j < 8; j++) dst[j] = __ldg(src + j);
            } else {
#pragma unroll
                for (int j = 0; j < 8; j++) dst[j] = make_float4(0.f, 0.f, 0.f, 0.f);
            }
        }
#pragma unroll
        for (int i = 0; i < 4; i++) {
            int idx = tid + i * 256;
            int wk = idx >> 4, wc = idx & 15;
            reinterpret_cast<float4*>(&sWs[wk * 64])[wc] =
                __ldg(reinterpret_cast<const float4*>(&W[(size_t)(kc + wk) * 64]) + wc);
        }
        __syncthreads();

#pragma unroll
        for (int k4 = 0; k4 < 64; k4 += 4) {
            float4 xv0 = *reinterpret_cast<const float4*>(&sX[rq * 68 + k4]);
            float4 xv1 = *reinterpret_cast<const float4*>(&sX[(rq + 32) * 68 + k4]);
            float4 xv2 = *reinterpret_cast<const float4*>(&sX[(rq + 64) * 68 + k4]);
            float4 xv3 = *reinterpret_cast<const float4*>(&sX[(rq + 96) * 68 + k4]);
            const float* px0 = reinterpret_cast<const float*>(&xv0);
            const float* px1 = reinterpret_cast<const float*>(&xv1);
            const float* px2 = reinterpret_cast<const float*>(&xv2);
            const float* px3 = reinterpret_cast<const float*>(&xv3);
#pragma unroll
            for (int kk = 0; kk < 4; kk++) {
                int k = k4 + kk;
                float4 w0 = *reinterpret_cast<const float4*>(&sWs[k * 64 + dbase]);
                float4 w1 = *reinterpret_cast<const float4*>(&sWs[k * 64 + dbase + 4]);
                float x0 = px0[kk], x1 = px1[kk], x2 = px2[kk], x3 = px3[kk];
                a0[0] += x0 * w0.x; a0[1] += x0 * w0.y; a0[2] += x0 * w0.z; a0[3] += x0 * w0.w;
                a0[4] += x0 * w1.x; a0[5] += x0 * w1.y; a0[6] += x0 * w1.z; a0[7] += x0 * w1.w;
                a1[0] += x1 * w0.x; a1[1] += x1 * w0.y; a1[2] += x1 * w0.z; a1[3] += x1 * w0.w;
                a1[4] += x1 * w1.x; a1[5] += x1 * w1.y; a1[6] += x1 * w1.z; a1[7] += x1 * w1.w;
                a2[0] += x2 * w0.x; a2[1] += x2 * w0.y; a2[2] += x2 * w0.z; a2[3] += x2 * w0.w;
                a2[4] += x2 * w1.x; a2[5] += x2 * w1.y; a2[6] += x2 * w1.z; a2[7] += x2 * w1.w;
                a3[0] += x3 * w0.x; a3[1] += x3 * w0.y; a3[2] += x3 * w0.z; a3[3] += x3 * w0.w;
                a3[4] += x3 * w1.x; a3[5] += x3 * w1.y; a3[6] += x3 * w1.z; a3[7] += x3 * w1.w;
            }
        }
        __syncthreads();
    }

    // BN + lrelu -> feat (overlay sX)
    {
        const float rs = rsqrtf(1.f + 1e-5f);
        float bv[8], gv[8], bev[8];
#pragma unroll
        for (int j = 0; j < 8; j++) {
            int d = dbase + j;
            bv[j]  = __ldg(&b[d]);
            gv[j]  = __ldg(&g[d]) * rs;
            bev[j] = __ldg(&beta[d]);
        }
#pragma unroll
        for (int q = 0; q < 4; q++) {
            float* acc = (q == 0) ? a0 : (q == 1) ? a1 : (q == 2) ? a2 : a3;
            int rr = rq + q * 32;
            float4 f0, f1;
            f0.x = lrelu((acc[0] + bv[0]) * gv[0] + bev[0]);
            f0.y = lrelu((acc[1] + bv[1]) * gv[1] + bev[1]);
            f0.z = lrelu((acc[2] + bv[2]) * gv[2] + bev[2]);
            f0.w = lrelu((acc[3] + bv[3]) * gv[3] + bev[3]);
            f1.x = lrelu((acc[4] + bv[4]) * gv[4] + bev[4]);
            f1.y = lrelu((acc[5] + bv[5]) * gv[5] + bev[5]);
            f1.z = lrelu((acc[6] + bv[6]) * gv[6] + bev[6]);
            f1.w = lrelu((acc[7] + bv[7]) * gv[7] + bev[7]);
            *reinterpret_cast<float4*>(&sX[rr * 68 + dbase])     = f0;
            *reinterpret_cast<float4*>(&sX[rr * 68 + dbase + 4]) = f1;
        }
    }
#pragma unroll
    for (int i = 0; i < 4; i++) {
        int idx = tid + i * 256;
        int wk = idx >> 4, wc = idx & 15;
        reinterpret_cast<float4*>(&sWs[wk * 64])[wc] =
            __ldg(reinterpret_cast<const float4*>(&Wg[(size_t)wk * 64]) + wc);
    }
    __syncthreads();

#pragma unroll
    for (int j = 0; j < 8; j++) {
        float bgv = __ldg(&bg[dbase + j]);
        a0[j] = bgv; a1[j] = bgv; a2[j] = bgv; a3[j] = bgv;
    }
#pragma unroll
    for (int k4 = 0; k4 < 64; k4 += 4) {
        float4 xv0 = *reinterpret_cast<const float4*>(&sX[rq * 68 + k4]);
        float4 xv1 = *reinterpret_cast<const float4*>(&sX[(rq + 32) * 68 + k4]);
        float4 xv2 = *reinterpret_cast<const float4*>(&sX[(rq + 64) * 68 + k4]);
        float4 xv3 = *reinterpret_cast<const float4*>(&sX[(rq + 96) * 68 + k4]);
        const float* px0 = reinterpret_cast<const float*>(&xv0);
        const float* px1 = reinterpret_cast<const float*>(&xv1);
        const float* px2 = reinterpret_cast<const float*>(&xv2);
        const float* px3 = reinterpret_cast<const float*>(&xv3);
#pragma unroll
        for (int kk = 0; kk < 4; kk++) {
            int k = k4 + kk;
            float4 w0 = *reinterpret_cast<const float4*>(&sWs[k * 64 + dbase]);
            float4 w1 = *reinterpret_cast<const float4*>(&sWs[k * 64 + dbase + 4]);
            float x0 = px0[kk], x1 = px1[kk], x2 = px2[kk], x3 = px3[kk];
            a0[0] += x0 * w0.x; a0[1] += x0 * w0.y; a0[2] += x0 * w0.z; a0[3] += x0 * w0.w;
            a0[4] += x0 * w1.x; a0[5] += x0 * w1.y; a0[6] += x0 * w1.z; a0[7] += x0 * w1.w;
            a1[0] += x1 * w0.x; a1[1] += x1 * w0.y; a1[2] += x1 * w0.z; a1[3] += x1 * w0.w;
            a1[4] += x1 * w1.x; a1[5] += x1 * w1.y; a1[6] += x1 * w1.z; a1[7] += x1 * w1.w;
            a2[0] += x2 * w0.x; a2[1] += x2 * w0.y; a2[2] += x2 * w0.z; a2[3] += x2 * w0.w;
            a2[4] += x2 * w1.x; a2[5] += x2 * w1.y; a2[6] += x2 * w1.z; a2[7] += x2 * w1.w;
            a3[0] += x3 * w0.x; a3[1] += x3 * w0.y; a3[2] += x3 * w0.z; a3[3] += x3 * w0.w;
            a3[4] += x3 * w1.x; a3[5] += x3 * w1.y; a3[6] += x3 * w1.z; a3[7] += x3 * w1.w;
        }
    }

#pragma unroll
    for (int q = 0; q < 4; q++) {
        float* acc = (q == 0) ? a0 : (q == 1) ? a1 : (q == 2) ? a2 : a3;
        int gr = r0 + rq + q * 32;
        if (gr < NI) {
            const float4* it = reinterpret_cast<const float4*>(item_emb + (size_t)gr * 64 + dbase);
            float4 i0 = __ldg(it), i1 = __ldg(it + 1);
            float4 o0, o1;
            o0.x = i0.x / (1.f + __expf(-acc[0]));
            o0.y = i0.y / (1.f + __expf(-acc[1]));
            o0.z = i0.z / (1.f + __expf(-acc[2]));
            o0.w = i0.w / (1.f + __expf(-acc[3]));
            o1.x = i1.x / (1.f + __expf(-acc[4]));
            o1.y = i1.y / (1.f + __expf(-acc[5]));
            o1.z = i1.z / (1.f + __expf(-acc[6]));
            o1.w = i1.w / (1.f + __expf(-acc[7]));
            float4* dst = reinterpret_cast<float4*>(out + (size_t)gr * 64 + dbase);
            dst[0] = o0; dst[1] = o1;
        }
    }
}

// ---------------- attention fusion over a row range (writes out[1..3]) --------
__global__ __launch_bounds__(256, 2)
void att_kernel(const float* __restrict__ img_ui, const float* __restrict__ txt_ui,
                const float* __restrict__ W1, const float* __restrict__ b1,
                const float* __restrict__ w2, float* __restrict__ out,
                int r_begin, int r_end) {
    __shared__ float sei[4][64], set_[4][64];
    __shared__ float wsum[8][2];
    int d    = threadIdx.x & 63;
    int sub  = threadIdx.x >> 6;
    int warp = threadIdx.x >> 5;
    int lane = threadIdx.x & 31;

    float Wc[64];
#pragma unroll
    for (int k = 0; k < 64; k++) Wc[k] = __ldg(&W1[k * 64 + d]);
    float b1d = __ldg(&b1[d]);
    float w2d = __ldg(&w2[d]);

    int r0 = r_begin + blockIdx.x * 128;
#pragma unroll 1
    for (int i = 0; i < 32; i++) {
        int r = r0 + i * 4 + sub;
        bool valid = r < r_end;
        size_t base = (size_t)r * 64 + d;
        float ei = valid ? __ldg(&img_ui[base]) : 0.f;
        float et = valid ? __ldg(&txt_ui[base]) : 0.f;
        sei[sub][d]  = ei;
        set_[sub][d] = et;
        __syncthreads();

        float hi = b1d, ht = b1d;
#pragma unroll
        for (int k = 0; k < 64; k += 4) {
            float4 a = *reinterpret_cast<const float4*>(&sei[sub][k]);
            float4 b = *reinterpret_cast<const float4*>(&set_[sub][k]);
            hi += a.x * Wc[k] + a.y * Wc[k + 1] + a.z * Wc[k + 2] + a.w * Wc[k + 3];
            ht += b.x * Wc[k] + b.y * Wc[k + 1] + b.z * Wc[k + 2] + b.w * Wc[k + 3];
        }
        hi = lrelu(hi) * w2d;
        ht = lrelu(ht) * w2d;
#pragma unroll
        for (int o = 16; o; o >>= 1) {
            hi += __shfl_xor_sync(0xffffffffu, hi, o);
            ht += __shfl_xor_sync(0xffffffffu, ht, o);
        }
        if (lane == 0) { wsum[warp][0] = hi; wsum[warp][1] = ht; }
        __syncthreads();
        int wbase = sub * 2;
        float si = wsum[wbase][0] + wsum[wbase + 1][0];
        float st = wsum[wbase][1] + wsum[wbase + 1][1];
        float wimg = 1.f / (1.f + __expf(st - si));
        float common = wimg * ei + (1.f - wimg) * et;

        if (valid) {
            out[(size_t)1 * NN * DD + base] = ei - common;
            out[(size_t)2 * NN * DD + base] = et - common;
            out[(size_t)3 * NN * DD + base] = common;
        }
        __syncthreads();
    }
}

// ---------------- driver ------------------------------------------------------
static inline int g256(long long n) { return (int)((n + 255) / 256); }

extern "C" void kernel_launch(void* const* d_in, const int* in_sizes, int n_in,
                              void* d_out, int out_size) {
    const float* user_emb  = (const float*)d_in[0];
    const float* item_emb  = (const float*)d_in[1];
    const float* image_emb = (const float*)d_in[2];
    const float* text_emb  = (const float*)d_in[3];
    const float* W_img = (const float*)d_in[4];
    const float* b_img = (const float*)d_in[5];
    const float* bng_img = (const float*)d_in[6];
    const float* bnb_img = (const float*)d_in[7];
    const float* W_txt = (const float*)d_in[8];
    const float* b_txt = (const float*)d_in[9];
    const float* bng_txt = (const float*)d_in[10];
    const float* bnb_txt = (const float*)d_in[11];
    const float* W_gi = (const float*)d_in[12];
    const float* b_gi = (const float*)d_in[13];
    const float* W_gt = (const float*)d_in[14];
    const float* b_gt = (const float*)d_in[15];
    const float* W_c1 = (const float*)d_in[16];
    const float* b_c1 = (const float*)d_in[17];
    const float* w_c2 = (const float*)d_in[18];
    const float* ui_vals = (const float*)d_in[19];
    const float* R_vals  = (const float*)d_in[20];
    const float* ii_i_vals = (const float*)d_in[21];
    const float* ii_t_vals = (const float*)d_in[22];
    const int* ui_rows = (const int*)d_in[23];
    const int* ui_cols = (const int*)d_in[24];
    const int* R_rows  = (const int*)d_in[25];
    const int* R_cols  = (const int*)d_in[26];
    const int* ii_i_rows = (const int*)d_in[27];
    const int* ii_i_cols = (const int*)d_in[28];
    const int* ii_t_rows = (const int*)d_in[29];
    const int* ii_t_cols = (const int*)d_in[30];

    float* out = (float*)d_out;

    void* p;
    cudaGetSymbolAddress(&p, g_cat1);   float* cat1   = (float*)p;
    cudaGetSymbolAddress(&p, g_cat2);   float* cat2   = (float*)p;
    cudaGetSymbolAddress(&p, g_img_ui); float* img_ui = (float*)p;
    cudaGetSymbolAddress(&p, g_txt_ui); float* txt_ui = (float*)p;
    cudaGetSymbolAddress(&p, g_gi0);    float* gi0    = (float*)p;
    cudaGetSymbolAddress(&p, g_gi1);    float* gi1    = (float*)p;
    cudaGetSymbolAddress(&p, g_gt0);    float* gt0    = (float*)p;
    cudaGetSymbolAddress(&p, g_gt1);    float* gt1    = (float*)p;

    float* img_items = img_ui + (size_t)NU * DD;
    float* txt_items = txt_ui + (size_t)NU * DD;

    static cudaStream_t sA = nullptr, sB = nullptr, sC = nullptr;
    static cudaEvent_t eFork = nullptr, eA = nullptr, eB = nullptr, eC = nullptr;
    static cudaEvent_t eBh = nullptr, eCh = nullptr;
    if (!sA) {
        cudaStreamCreateWithFlags(&sA, cudaStreamNonBlocking);
        cudaStreamCreateWithFlags(&sB, cudaStreamNonBlocking);
        cudaStreamCreateWithFlags(&sC, cudaStreamNonBlocking);
        cudaEventCreateWithFlags(&eFork, cudaEventDisableTiming);
        cudaEventCreateWithFlags(&eA, cudaEventDisableTiming);
        cudaEventCreateWithFlags(&eB, cudaEventDisableTiming);
        cudaEventCreateWithFlags(&eC, cudaEventDisableTiming);
        cudaEventCreateWithFlags(&eBh, cudaEventDisableTiming);
        cudaEventCreateWithFlags(&eCh, cudaEventDisableTiming);
    }

    const int G_UI = NNZ_UI / 32;          // 31250
    const int G_II = NNZ_II / 32;          //  9375
    const int G_R  = NNZ_R * 16 / 256;     // 50000
    const size_t NNB = (size_t)NN * DD * sizeof(float);
    const size_t NIB = (size_t)NI * DD * sizeof(float);

    cudaEventRecord(eFork, 0);
    cudaStreamWaitEvent(sA, eFork, 0);
    cudaStreamWaitEvent(sB, eFork, 0);
    cudaStreamWaitEvent(sC, eFork, 0);

    // chain A: ui GCN -> out[0]
    cudaMemsetAsync(cat1, 0, NNB, sA);
    cudaMemsetAsync(cat2, 0, NNB, sA);
    spmm_cat_kernel<<<G_UI, 256, 0, sA>>>(ui_rows, ui_cols, ui_vals, item_emb, user_emb, cat1, NNZ_UI);
    spmm2_kernel<<<G_UI, 256, 0, sA>>>(ui_rows, ui_cols, ui_vals, cat1, cat2, NNZ_UI);
    mean3_cat_kernel<<<g256((long long)NN * 16), 256, 0, sA>>>(item_emb, user_emb, cat1, cat2, out);
    cudaEventRecord(eA, sA);

    // chain B: image branch up through ii-hop2
    cudaMemsetAsync(img_ui, 0, NNB, sB);
    cudaMemsetAsync(gi1, 0, NIB, sB);
    projgate_kernel<512><<<(NI + 127) / 128, 256, 0, sB>>>(image_emb, W_img, b_img, bng_img, bnb_img,
                                                           W_gi, b_gi, item_emb, gi0);
    spmm2_kernel<<<G_II, 256, 0, sB>>>(ii_i_rows, ii_i_cols, ii_i_vals, gi0, gi1, NNZ_II);
    spmm2_kernel<<<G_II, 256, 0, sB>>>(ii_i_rows, ii_i_cols, ii_i_vals, gi1, img_items, NNZ_II);
    cudaEventRecord(eBh, sB);

    // chain C: text branch up through ii-hop2
    cudaMemsetAsync(txt_ui, 0, NNB, sC);
    cudaMemsetAsync(gt1, 0, NIB, sC);
    projgate_kernel<384><<<(NI + 127) / 128, 256, 0, sC>>>(text_emb, W_txt, b_txt, bng_txt, bnb_txt,
                                                           W_gt, b_gt, item_emb, gt0);
    spmm2_kernel<<<G_II, 256, 0, sC>>>(ii_t_rows, ii_t_cols, ii_t_vals, gt0, gt1, NNZ_II);
    spmm2_kernel<<<G_II, 256, 0, sC>>>(ii_t_rows, ii_t_cols, ii_t_vals, gt1, txt_items, NNZ_II);
    cudaEventRecord(eCh, sC);

    // B: after both item halves ready, dualR (user rows) then att over user rows
    cudaStreamWaitEvent(sB, eCh, 0);
    spmm_dualR_kernel<<<G_R, 256, 0, sB>>>(R_rows, R_cols, R_vals, img_items, txt_items,
                                           img_ui, txt_ui, NNZ_R);
    att_kernel<<<(NU + 127) / 128, 256, 0, sB>>>(img_ui, txt_ui, W_c1, b_c1, w_c2, out, 0, NU);
    cudaEventRecord(eB, sB);

    // C: att over item rows runs concurrently with dualR
    cudaStreamWaitEvent(sC, eBh, 0);
    att_kernel<<<(NI + 127) / 128, 256, 0, sC>>>(img_ui, txt_ui, W_c1, b_c1, w_c2, out, NU, NN);
    cudaEventRecord(eC, sC);

    // join everything back to capture stream
    cudaStreamWaitEvent(0, eA, 0);
    cudaStreamWaitEvent(0, eB, 0);
    cudaStreamWaitEvent(0, eC, 0);
}

// round 7
// speedup vs baseline: 1.8870x; 1.2011x over previous
#include <cuda_runtime.h>
#include <math.h>
#include <stdint.h>

#define NU 50000
#define NI 30000
#define NN 80000
#define DD 64

#define NNZ_UI 1000000
#define NNZ_R  800000
#define NNZ_II 300000

// ---------------- scratch (static device globals) -----------------------------
__device__ float g_cat1[NN * DD];
__device__ float g_cat2[NN * DD];
__device__ float g_img_ui[NN * DD];
__device__ float g_txt_ui[NN * DD];
__device__ float g_gi0[NI * DD];
__device__ float g_gi1[NI * DD];
__device__ float g_gt0[NI * DD];
__device__ float g_gt1[NI * DD];

__device__ __forceinline__ float lrelu(float x) { return x >= 0.f ? x : 0.01f * x; }

__device__ __forceinline__ void red4(float* dst, float v, float4 x) {
    asm volatile("red.global.add.v4.f32 [%0], {%1, %2, %3, %4};"
                 :: "l"(dst), "f"(v * x.x), "f"(v * x.y), "f"(v * x.z), "f"(v * x.w)
                 : "memory");
}

__device__ __forceinline__ uint32_t f2tf32(float f) {
    uint32_t r;
    asm("cvt.rna.tf32.f32 %0, %1;" : "=r"(r) : "f"(f));
    return r;
}

__device__ __forceinline__ void mma_tf32(float& c0, float& c1, float& c2, float& c3,
                                         uint32_t a0, uint32_t a1, uint32_t a2, uint32_t a3,
                                         uint32_t b0, uint32_t b1) {
    asm("mma.sync.aligned.m16n8k8.row.col.f32.tf32.tf32.f32 "
        "{%0,%1,%2,%3}, {%4,%5,%6,%7}, {%8,%9}, {%0,%1,%2,%3};"
        : "+f"(c0), "+f"(c1), "+f"(c2), "+f"(c3)
        : "r"(a0), "r"(a1), "r"(a2), "r"(a3), "r"(b0), "r"(b1));
}

// ---------------- ui hop1: gathers from virtual concat [item;user] ------------
__global__ void spmm_cat_kernel(const int* __restrict__ rows, const int* __restrict__ cols,
                                const float* __restrict__ vals,
                                const float* __restrict__ item_emb,
                                const float* __restrict__ user_emb,
                                float* __restrict__ out, int nnz) {
    int t = blockIdx.x * blockDim.x + threadIdx.x;
    int j = t & 15;
    int e0 = (t >> 4) * 2;
    if (e0 >= nnz) return;

    int c0 = __ldg(&cols[e0]);
    int c1 = __ldg(&cols[e0 + 1]);
    const float4* p0 = (c0 < NI)
        ? reinterpret_cast<const float4*>(item_emb) + (size_t)c0 * 16
        : reinterpret_cast<const float4*>(user_emb) + (size_t)(c0 - NI) * 16;
    const float4* p1 = (c1 < NI)
        ? reinterpret_cast<const float4*>(item_emb) + (size_t)c1 * 16
        : reinterpret_cast<const float4*>(user_emb) + (size_t)(c1 - NI) * 16;
    float4 x0 = __ldg(p0 + j);
    float4 x1 = __ldg(p1 + j);
    int   r0 = __ldg(&rows[e0]);
    int   r1 = __ldg(&rows[e0 + 1]);
    float v0 = __ldg(&vals[e0]);
    float v1 = __ldg(&vals[e0 + 1]);
    red4(out + (size_t)r0 * 64 + j * 4, v0, x0);
    red4(out + (size_t)r1 * 64 + j * 4, v1, x1);
}

// ---------------- generic spmm ------------------------------------------------
__global__ void spmm2_kernel(const int* __restrict__ rows, const int* __restrict__ cols,
                             const float* __restrict__ vals, const float* __restrict__ x,
                             float* __restrict__ out, int nnz) {
    int t = blockIdx.x * blockDim.x + threadIdx.x;
    int j = t & 15;
    int e0 = (t >> 4) * 2;
    if (e0 >= nnz) return;

    int c0 = __ldg(&cols[e0]);
    int c1 = __ldg(&cols[e0 + 1]);
    float4 x0 = __ldg(reinterpret_cast<const float4*>(x) + (size_t)c0 * 16 + j);
    float4 x1 = __ldg(reinterpret_cast<const float4*>(x) + (size_t)c1 * 16 + j);
    int   r0 = __ldg(&rows[e0]);
    int   r1 = __ldg(&rows[e0 + 1]);
    float v0 = __ldg(&vals[e0]);
    float v1 = __ldg(&vals[e0 + 1]);
    red4(out + (size_t)r0 * 64 + j * 4, v0, x0);
    red4(out + (size_t)r1 * 64 + j * 4, v1, x1);
}

// ---------------- dual spmm over R --------------------------------------------
__global__ void spmm_dualR_kernel(const int* __restrict__ rows, const int* __restrict__ cols,
                                  const float* __restrict__ vals,
                                  const float* __restrict__ xi, const float* __restrict__ xt,
                                  float* __restrict__ oi, float* __restrict__ ot, int nnz) {
    int t = blockIdx.x * blockDim.x + threadIdx.x;
    int j = t & 15;
    int e = t >> 4;
    if (e >= nnz) return;

    int   c = __ldg(&cols[e]);
    int   r = __ldg(&rows[e]);
    float v = __ldg(&vals[e]);
    float4 a = __ldg(reinterpret_cast<const float4*>(xi) + (size_t)c * 16 + j);
    float4 b = __ldg(reinterpret_cast<const float4*>(xt) + (size_t)c * 16 + j);
    red4(oi + (size_t)r * 64 + j * 4, v, a);
    red4(ot + (size_t)r * 64 + j * 4, v, b);
}

// ---------------- mean3 -> out[0] ----------------------------------------------
__global__ void mean3_cat_kernel(const float* __restrict__ item_emb,
                                 const float* __restrict__ user_emb,
                                 const float* __restrict__ b, const float* __restrict__ c,
                                 float* __restrict__ out) {
    int i = blockIdx.x * blockDim.x + threadIdx.x;
    const int NI4 = NI * 16, NN4 = NN * 16;
    if (i >= NN4) return;
    float4 A = (i < NI4) ? __ldg(reinterpret_cast<const float4*>(item_emb) + i)
                         : __ldg(reinterpret_cast<const float4*>(user_emb) + (i - NI4));
    float4 B = reinterpret_cast<const float4*>(b)[i];
    float4 C = reinterpret_cast<const float4*>(c)[i];
    const float s = 1.f / 3.f;
    reinterpret_cast<float4*>(out)[i] =
        make_float4((A.x + B.x + C.x) * s, (A.y + B.y + C.y) * s,
                    (A.z + B.z + C.z) * s, (A.w + B.w + C.w) * s);
}

// ---------------- tf32 tensor-core projection + BN + lrelu + gate --------------
// Block = 256 thr (8 warps). Tile 128 rows x 64 cols. Warp w: rows w*16..w*16+15.
// smem X: [128 rows][64 k] tf32, pitch 68. smem Wt: [64 n][64 k] tf32, pitch 68 (transposed).
#define XPITCH 68
template <int F>
__global__ __launch_bounds__(256)
void projgate_kernel(const float* __restrict__ x, const float* __restrict__ W,
                     const float* __restrict__ b, const float* __restrict__ g,
                     const float* __restrict__ beta,
                     const float* __restrict__ Wg, const float* __restrict__ bg,
                     const float* __restrict__ item_emb,
                     float* __restrict__ out) {
    __shared__ uint32_t sX[128 * XPITCH];
    __shared__ uint32_t sWt[64 * XPITCH];

    const int tid  = threadIdx.x;
    const int warp = tid >> 5;
    const int lane = tid & 31;
    const int gq   = lane >> 2;     // groupID 0..7
    const int tg   = lane & 3;      // thread-in-group 0..3
    const int wr   = warp * 16;     // warp row base within tile
    const int r0   = blockIdx.x * 128;

    float acc[8][4];
#pragma unroll
    for (int nb = 0; nb < 8; nb++)
#pragma unroll
        for (int i = 0; i < 4; i++) acc[nb][i] = 0.f;

    for (int kc = 0; kc < F; kc += 64) {
        // ---- stage X chunk as tf32: thread -> row tid>>1, half tid&1 ----
        {
            int lr = tid >> 1, half = tid & 1;
            int gr = r0 + lr;
            uint32_t* dst = &sX[lr * XPITCH + half * 32];
            if (gr < NI) {
                const float4* src = reinterpret_cast<const float4*>(x + (size_t)gr * F + kc) + half * 8;
#pragma unroll
                for (int i = 0; i < 8; i++) {
                    float4 v = __ldg(src + i);
                    dst[i * 4 + 0] = f2tf32(v.x);
                    dst[i * 4 + 1] = f2tf32(v.y);
                    dst[i * 4 + 2] = f2tf32(v.z);
                    dst[i * 4 + 3] = f2tf32(v.w);
                }
            } else {
#pragma unroll
                for (int i = 0; i < 32; i++) dst[i] = 0u;
            }
        }
        // ---- stage W chunk transposed as tf32: thread -> k row tid>>2, 16 n ----
        {
            int wk = tid >> 2, ng = (tid & 3) * 16;
            const float4* src = reinterpret_cast<const float4*>(&W[(size_t)(kc + wk) * 64 + ng]);
#pragma unroll
            for (int i = 0; i < 4; i++) {
                float4 v = __ldg(src + i);
                int n = ng + i * 4;
                sWt[(n + 0) * XPITCH + wk] = f2tf32(v.x);
                sWt[(n + 1) * XPITCH + wk] = f2tf32(v.y);
                sWt[(n + 2) * XPITCH + wk] = f2tf32(v.z);
                sWt[(n + 3) * XPITCH + wk] = f2tf32(v.w);
            }
        }
        __syncthreads();

#pragma unroll
        for (int ks = 0; ks < 8; ks++) {
            int k4 = ks * 8;
            uint32_t a0 = sX[(wr + gq) * XPITCH + k4 + tg];
            uint32_t a1 = sX[(wr + gq + 8) * XPITCH + k4 + tg];
            uint32_t a2 = sX[(wr + gq) * XPITCH + k4 + tg + 4];
            uint32_t a3 = sX[(wr + gq + 8) * XPITCH + k4 + tg + 4];
#pragma unroll
            for (int nb = 0; nb < 8; nb++) {
                uint32_t b0 = sWt[(nb * 8 + gq) * XPITCH + k4 + tg];
                uint32_t b1 = sWt[(nb * 8 + gq) * XPITCH + k4 + tg + 4];
                mma_tf32(acc[nb][0], acc[nb][1], acc[nb][2], acc[nb][3],
                         a0, a1, a2, a3, b0, b1);
            }
        }
        __syncthreads();
    }

    // ---- BN + lrelu -> feat (tf32) back into sX; stage Wg transposed ----
    const float rs = rsqrtf(1.f + 1e-5f);
#pragma unroll
    for (int nb = 0; nb < 8; nb++) {
        int c0 = nb * 8 + 2 * tg;
        int c1 = c0 + 1;
        float s0 = __ldg(&g[c0]) * rs, s1 = __ldg(&g[c1]) * rs;
        float bb0 = __ldg(&b[c0]), bb1 = __ldg(&b[c1]);
        float be0 = __ldg(&beta[c0]), be1 = __ldg(&beta[c1]);
        float f00 = lrelu((acc[nb][0] + bb0) * s0 + be0);
        float f01 = lrelu((acc[nb][1] + bb1) * s1 + be1);
        float f10 = lrelu((acc[nb][2] + bb0) * s0 + be0);
        float f11 = lrelu((acc[nb][3] + bb1) * s1 + be1);
        sX[(wr + gq) * XPITCH + c0]     = f2tf32(f00);
        sX[(wr + gq) * XPITCH + c1]     = f2tf32(f01);
        sX[(wr + gq + 8) * XPITCH + c0] = f2tf32(f10);
        sX[(wr + gq + 8) * XPITCH + c1] = f2tf32(f11);
        acc[nb][0] = 0.f; acc[nb][1] = 0.f; acc[nb][2] = 0.f; acc[nb][3] = 0.f;
    }
    {
        int wk = tid >> 2, ng = (tid & 3) * 16;
        const float4* src = reinterpret_cast<const float4*>(&Wg[(size_t)wk * 64 + ng]);
#pragma unroll
        for (int i = 0; i < 4; i++) {
            float4 v = __ldg(src + i);
            int n = ng + i * 4;
            sWt[(n + 0) * XPITCH + wk] = f2tf32(v.x);
            sWt[(n + 1) * XPITCH + wk] = f2tf32(v.y);
            sWt[(n + 2) * XPITCH + wk] = f2tf32(v.z);
            sWt[(n + 3) * XPITCH + wk] = f2tf32(v.w);
        }
    }
    __syncthreads();

    // ---- gate GEMM: feat @ Wg ----
#pragma unroll
    for (int ks = 0; ks < 8; ks++) {
        int k4 = ks * 8;
        uint32_t a0 = sX[(wr + gq) * XPITCH + k4 + tg];
        uint32_t a1 = sX[(wr + gq + 8) * XPITCH + k4 + tg];
        uint32_t a2 = sX[(wr + gq) * XPITCH + k4 + tg + 4];
        uint32_t a3 = sX[(wr + gq + 8) * XPITCH + k4 + tg + 4];
#pragma unroll
        for (int nb = 0; nb < 8; nb++) {
            uint32_t b0 = sWt[(nb * 8 + gq) * XPITCH + k4 + tg];
            uint32_t b1 = sWt[(nb * 8 + gq) * XPITCH + k4 + tg + 4];
            mma_tf32(acc[nb][0], acc[nb][1], acc[nb][2], acc[nb][3],
                     a0, a1, a2, a3, b0, b1);
        }
    }

    // ---- sigmoid gate * item_emb -> out ----
    int rlo = r0 + wr + gq;
    int rhi = rlo + 8;
#pragma unroll
    for (int nb = 0; nb < 8; nb++) {
        int c0 = nb * 8 + 2 * tg;
        float bg0 = __ldg(&bg[c0]), bg1 = __ldg(&bg[c0 + 1]);
        if (rlo < NI) {
            float2 it = *reinterpret_cast<const float2*>(item_emb + (size_t)rlo * 64 + c0);
            float2 o;
            o.x = it.x / (1.f + __expf(-(acc[nb][0] + bg0)));
            o.y = it.y / (1.f + __expf(-(acc[nb][1] + bg1)));
            *reinterpret_cast<float2*>(out + (size_t)rlo * 64 + c0) = o;
        }
        if (rhi < NI) {
            float2 it = *reinterpret_cast<const float2*>(item_emb + (size_t)rhi * 64 + c0);
            float2 o;
            o.x = it.x / (1.f + __expf(-(acc[nb][2] + bg0)));
            o.y = it.y / (1.f + __expf(-(acc[nb][3] + bg1)));
            *reinterpret_cast<float2*>(out + (size_t)rhi * 64 + c0) = o;
        }
    }
}

// ---------------- attention fusion over a row range (writes out[1..3]) --------
__global__ __launch_bounds__(256, 2)
void att_kernel(const float* __restrict__ img_ui, const float* __restrict__ txt_ui,
                const float* __restrict__ W1, const float* __restrict__ b1,
                const float* __restrict__ w2, float* __restrict__ out,
                int r_begin, int r_end) {
    __shared__ float sei[4][64], set_[4][64];
    __shared__ float wsum[8][2];
    int d    = threadIdx.x & 63;
    int sub  = threadIdx.x >> 6;
    int warp = threadIdx.x >> 5;
    int lane = threadIdx.x & 31;

    float Wc[64];
#pragma unroll
    for (int k = 0; k < 64; k++) Wc[k] = __ldg(&W1[k * 64 + d]);
    float b1d = __ldg(&b1[d]);
    float w2d = __ldg(&w2[d]);

    int r0 = r_begin + blockIdx.x * 128;
#pragma unroll 1
    for (int i = 0; i < 32; i++) {
        int r = r0 + i * 4 + sub;
        bool valid = r < r_end;
        size_t base = (size_t)r * 64 + d;
        float ei = valid ? __ldg(&img_ui[base]) : 0.f;
        float et = valid ? __ldg(&txt_ui[base]) : 0.f;
        sei[sub][d]  = ei;
        set_[sub][d] = et;
        __syncthreads();

        float hi = b1d, ht = b1d;
#pragma unroll
        for (int k = 0; k < 64; k += 4) {
            float4 a = *reinterpret_cast<const float4*>(&sei[sub][k]);
            float4 b = *reinterpret_cast<const float4*>(&set_[sub][k]);
            hi += a.x * Wc[k] + a.y * Wc[k + 1] + a.z * Wc[k + 2] + a.w * Wc[k + 3];
            ht += b.x * Wc[k] + b.y * Wc[k + 1] + b.z * Wc[k + 2] + b.w * Wc[k + 3];
        }
        hi = lrelu(hi) * w2d;
        ht = lrelu(ht) * w2d;
#pragma unroll
        for (int o = 16; o; o >>= 1) {
            hi += __shfl_xor_sync(0xffffffffu, hi, o);
            ht += __shfl_xor_sync(0xffffffffu, ht, o);
        }
        if (lane == 0) { wsum[warp][0] = hi; wsum[warp][1] = ht; }
        __syncthreads();
        int wbase = sub * 2;
        float si = wsum[wbase][0] + wsum[wbase + 1][0];
        float st = wsum[wbase][1] + wsum[wbase + 1][1];
        float wimg = 1.f / (1.f + __expf(st - si));
        float common = wimg * ei + (1.f - wimg) * et;

        if (valid) {
            out[(size_t)1 * NN * DD + base] = ei - common;
            out[(size_t)2 * NN * DD + base] = et - common;
            out[(size_t)3 * NN * DD + base] = common;
        }
        __syncthreads();
    }
}

// ---------------- driver ------------------------------------------------------
static inline int g256(long long n) { return (int)((n + 255) / 256); }

extern "C" void kernel_launch(void* const* d_in, const int* in_sizes, int n_in,
                              void* d_out, int out_size) {
    const float* user_emb  = (const float*)d_in[0];
    const float* item_emb  = (const float*)d_in[1];
    const float* image_emb = (const float*)d_in[2];
    const float* text_emb  = (const float*)d_in[3];
    const float* W_img = (const float*)d_in[4];
    const float* b_img = (const float*)d_in[5];
    const float* bng_img = (const float*)d_in[6];
    const float* bnb_img = (const float*)d_in[7];
    const float* W_txt = (const float*)d_in[8];
    const float* b_txt = (const float*)d_in[9];
    const float* bng_txt = (const float*)d_in[10];
    const float* bnb_txt = (const float*)d_in[11];
    const float* W_gi = (const float*)d_in[12];
    const float* b_gi = (const float*)d_in[13];
    const float* W_gt = (const float*)d_in[14];
    const float* b_gt = (const float*)d_in[15];
    const float* W_c1 = (const float*)d_in[16];
    const float* b_c1 = (const float*)d_in[17];
    const float* w_c2 = (const float*)d_in[18];
    const float* ui_vals = (const float*)d_in[19];
    const float* R_vals  = (const float*)d_in[20];
    const float* ii_i_vals = (const float*)d_in[21];
    const float* ii_t_vals = (const float*)d_in[22];
    const int* ui_rows = (const int*)d_in[23];
    const int* ui_cols = (const int*)d_in[24];
    const int* R_rows  = (const int*)d_in[25];
    const int* R_cols  = (const int*)d_in[26];
    const int* ii_i_rows = (const int*)d_in[27];
    const int* ii_i_cols = (const int*)d_in[28];
    const int* ii_t_rows = (const int*)d_in[29];
    const int* ii_t_cols = (const int*)d_in[30];

    float* out = (float*)d_out;

    void* p;
    cudaGetSymbolAddress(&p, g_cat1);   float* cat1   = (float*)p;
    cudaGetSymbolAddress(&p, g_cat2);   float* cat2   = (float*)p;
    cudaGetSymbolAddress(&p, g_img_ui); float* img_ui = (float*)p;
    cudaGetSymbolAddress(&p, g_txt_ui); float* txt_ui = (float*)p;
    cudaGetSymbolAddress(&p, g_gi0);    float* gi0    = (float*)p;
    cudaGetSymbolAddress(&p, g_gi1);    float* gi1    = (float*)p;
    cudaGetSymbolAddress(&p, g_gt0);    float* gt0    = (float*)p;
    cudaGetSymbolAddress(&p, g_gt1);    float* gt1    = (float*)p;

    float* img_items = img_ui + (size_t)NU * DD;
    float* txt_items = txt_ui + (size_t)NU * DD;

    static cudaStream_t sA = nullptr, sB = nullptr, sC = nullptr;
    static cudaEvent_t eFork = nullptr, eA = nullptr, eB = nullptr, eC = nullptr;
    static cudaEvent_t eBh = nullptr, eCh = nullptr;
    if (!sA) {
        cudaStreamCreateWithFlags(&sA, cudaStreamNonBlocking);
        cudaStreamCreateWithFlags(&sB, cudaStreamNonBlocking);
        cudaStreamCreateWithFlags(&sC, cudaStreamNonBlocking);
        cudaEventCreateWithFlags(&eFork, cudaEventDisableTiming);
        cudaEventCreateWithFlags(&eA, cudaEventDisableTiming);
        cudaEventCreateWithFlags(&eB, cudaEventDisableTiming);
        cudaEventCreateWithFlags(&eC, cudaEventDisableTiming);
        cudaEventCreateWithFlags(&eBh, cudaEventDisableTiming);
        cudaEventCreateWithFlags(&eCh, cudaEventDisableTiming);
    }

    const int G_UI = NNZ_UI / 32;          // 31250
    const int G_II = NNZ_II / 32;          //  9375
    const int G_R  = NNZ_R * 16 / 256;     // 50000
    const size_t NNB = (size_t)NN * DD * sizeof(float);
    const size_t NIB = (size_t)NI * DD * sizeof(float);

    cudaEventRecord(eFork, 0);
    cudaStreamWaitEvent(sA, eFork, 0);
    cudaStreamWaitEvent(sB, eFork, 0);
    cudaStreamWaitEvent(sC, eFork, 0);

    // chain A: ui GCN -> out[0]
    cudaMemsetAsync(cat1, 0, NNB, sA);
    cudaMemsetAsync(cat2, 0, NNB, sA);
    spmm_cat_kernel<<<G_UI, 256, 0, sA>>>(ui_rows, ui_cols, ui_vals, item_emb, user_emb, cat1, NNZ_UI);
    spmm2_kernel<<<G_UI, 256, 0, sA>>>(ui_rows, ui_cols, ui_vals, cat1, cat2, NNZ_UI);
    mean3_cat_kernel<<<g256((long long)NN * 16), 256, 0, sA>>>(item_emb, user_emb, cat1, cat2, out);
    cudaEventRecord(eA, sA);

    // chain B: image branch up through ii-hop2
    cudaMemsetAsync(img_ui, 0, NNB, sB);
    cudaMemsetAsync(gi1, 0, NIB, sB);
    projgate_kernel<512><<<(NI + 127) / 128, 256, 0, sB>>>(image_emb, W_img, b_img, bng_img, bnb_img,
                                                           W_gi, b_gi, item_emb, gi0);
    spmm2_kernel<<<G_II, 256, 0, sB>>>(ii_i_rows, ii_i_cols, ii_i_vals, gi0, gi1, NNZ_II);
    spmm2_kernel<<<G_II, 256, 0, sB>>>(ii_i_rows, ii_i_cols, ii_i_vals, gi1, img_items, NNZ_II);
    cudaEventRecord(eBh, sB);

    // chain C: text branch up through ii-hop2
    cudaMemsetAsync(txt_ui, 0, NNB, sC);
    cudaMemsetAsync(gt1, 0, NIB, sC);
    projgate_kernel<384><<<(NI + 127) / 128, 256, 0, sC>>>(text_emb, W_txt, b_txt, bng_txt, bnb_txt,
                                                           W_gt, b_gt, item_emb, gt0);
    spmm2_kernel<<<G_II, 256, 0, sC>>>(ii_t_rows, ii_t_cols, ii_t_vals, gt0, gt1, NNZ_II);
    spmm2_kernel<<<G_II, 256, 0, sC>>>(ii_t_rows, ii_t_cols, ii_t_vals, gt1, txt_items, NNZ_II);
    cudaEventRecord(eCh, sC);

    // B: after both item halves ready, dualR (user rows) then att over user rows
    cudaStreamWaitEvent(sB, eCh, 0);
    spmm_dualR_kernel<<<G_R, 256, 0, sB>>>(R_rows, R_cols, R_vals, img_items, txt_items,
                                           img_ui, txt_ui, NNZ_R);
    att_kernel<<<(NU + 127) / 128, 256, 0, sB>>>(img_ui, txt_ui, W_c1, b_c1, w_c2, out, 0, NU);
    cudaEventRecord(eB, sB);

    // C: att over item rows runs concurrently with dualR
    cudaStreamWaitEvent(sC, eBh, 0);
    att_kernel<<<(NI + 127) / 128, 256, 0, sC>>>(img_ui, txt_ui, W_c1, b_c1, w_c2, out, NU, NN);
    cudaEventRecord(eC, sC);

    // join everything back to capture stream
    cudaStreamWaitEvent(0, eA, 0);
    cudaStreamWaitEvent(0, eB, 0);
    cudaStreamWaitEvent(0, eC, 0);
}

// round 8
// speedup vs baseline: 1.8932x; 1.0033x over previous
#include <cuda_runtime.h>
#include <math.h>
#include <stdint.h>

#define NU 50000
#define NI 30000
#define NN 80000
#define DD 64

#define NNZ_UI 1000000
#define NNZ_R  800000
#define NNZ_II 300000

// ---------------- scratch (static device globals) -----------------------------
__device__ float g_cat1[NN * DD];
__device__ float g_cat2[NN * DD];
__device__ float g_img_ui[NN * DD];
__device__ float g_txt_ui[NN * DD];
__device__ float g_gi0[NI * DD];
__device__ float g_gi1[NI * DD];
__device__ float g_gt0[NI * DD];
__device__ float g_gt1[NI * DD];

__device__ __forceinline__ float lrelu(float x) { return x >= 0.f ? x : 0.01f * x; }

__device__ __forceinline__ void red4(float* dst, float v, float4 x) {
    asm volatile("red.global.add.v4.f32 [%0], {%1, %2, %3, %4};"
                 :: "l"(dst), "f"(v * x.x), "f"(v * x.y), "f"(v * x.z), "f"(v * x.w)
                 : "memory");
}

__device__ __forceinline__ uint32_t f2tf32(float f) {
    uint32_t r;
    asm("cvt.rna.tf32.f32 %0, %1;" : "=r"(r) : "f"(f));
    return r;
}

__device__ __forceinline__ void mma_tf32(float& c0, float& c1, float& c2, float& c3,
                                         uint32_t a0, uint32_t a1, uint32_t a2, uint32_t a3,
                                         uint32_t b0, uint32_t b1) {
    asm("mma.sync.aligned.m16n8k8.row.col.f32.tf32.tf32.f32 "
        "{%0,%1,%2,%3}, {%4,%5,%6,%7}, {%8,%9}, {%0,%1,%2,%3};"
        : "+f"(c0), "+f"(c1), "+f"(c2), "+f"(c3)
        : "r"(a0), "r"(a1), "r"(a2), "r"(a3), "r"(b0), "r"(b1));
}

// ---------------- ui hop1: gathers from virtual concat [item;user] ------------
__global__ void spmm_cat_kernel(const int* __restrict__ rows, const int* __restrict__ cols,
                                const float* __restrict__ vals,
                                const float* __restrict__ item_emb,
                                const float* __restrict__ user_emb,
                                float* __restrict__ out, int nnz) {
    int t = blockIdx.x * blockDim.x + threadIdx.x;
    int j = t & 15;
    int e0 = (t >> 4) * 2;
    if (e0 >= nnz) return;

    int c0 = __ldg(&cols[e0]);
    int c1 = __ldg(&cols[e0 + 1]);
    const float4* p0 = (c0 < NI)
        ? reinterpret_cast<const float4*>(item_emb) + (size_t)c0 * 16
        : reinterpret_cast<const float4*>(user_emb) + (size_t)(c0 - NI) * 16;
    const float4* p1 = (c1 < NI)
        ? reinterpret_cast<const float4*>(item_emb) + (size_t)c1 * 16
        : reinterpret_cast<const float4*>(user_emb) + (size_t)(c1 - NI) * 16;
    float4 x0 = __ldg(p0 + j);
    float4 x1 = __ldg(p1 + j);
    int   r0 = __ldg(&rows[e0]);
    int   r1 = __ldg(&rows[e0 + 1]);
    float v0 = __ldg(&vals[e0]);
    float v1 = __ldg(&vals[e0 + 1]);
    red4(out + (size_t)r0 * 64 + j * 4, v0, x0);
    red4(out + (size_t)r1 * 64 + j * 4, v1, x1);
}

// ---------------- generic spmm ------------------------------------------------
__global__ void spmm2_kernel(const int* __restrict__ rows, const int* __restrict__ cols,
                             const float* __restrict__ vals, const float* __restrict__ x,
                             float* __restrict__ out, int nnz) {
    int t = blockIdx.x * blockDim.x + threadIdx.x;
    int j = t & 15;
    int e0 = (t >> 4) * 2;
    if (e0 >= nnz) return;

    int c0 = __ldg(&cols[e0]);
    int c1 = __ldg(&cols[e0 + 1]);
    float4 x0 = __ldg(reinterpret_cast<const float4*>(x) + (size_t)c0 * 16 + j);
    float4 x1 = __ldg(reinterpret_cast<const float4*>(x) + (size_t)c1 * 16 + j);
    int   r0 = __ldg(&rows[e0]);
    int   r1 = __ldg(&rows[e0 + 1]);
    float v0 = __ldg(&vals[e0]);
    float v1 = __ldg(&vals[e0 + 1]);
    red4(out + (size_t)r0 * 64 + j * 4, v0, x0);
    red4(out + (size_t)r1 * 64 + j * 4, v1, x1);
}

// ---------------- dual spmm over R --------------------------------------------
__global__ void spmm_dualR_kernel(const int* __restrict__ rows, const int* __restrict__ cols,
                                  const float* __restrict__ vals,
                                  const float* __restrict__ xi, const float* __restrict__ xt,
                                  float* __restrict__ oi, float* __restrict__ ot, int nnz) {
    int t = blockIdx.x * blockDim.x + threadIdx.x;
    int j = t & 15;
    int e = t >> 4;
    if (e >= nnz) return;

    int   c = __ldg(&cols[e]);
    int   r = __ldg(&rows[e]);
    float v = __ldg(&vals[e]);
    float4 a = __ldg(reinterpret_cast<const float4*>(xi) + (size_t)c * 16 + j);
    float4 b = __ldg(reinterpret_cast<const float4*>(xt) + (size_t)c * 16 + j);
    red4(oi + (size_t)r * 64 + j * 4, v, a);
    red4(ot + (size_t)r * 64 + j * 4, v, b);
}

// ---------------- mean3 -> out[0] ----------------------------------------------
__global__ void mean3_cat_kernel(const float* __restrict__ item_emb,
                                 const float* __restrict__ user_emb,
                                 const float* __restrict__ b, const float* __restrict__ c,
                                 float* __restrict__ out) {
    int i = blockIdx.x * blockDim.x + threadIdx.x;
    const int NI4 = NI * 16, NN4 = NN * 16;
    if (i >= NN4) return;
    float4 A = (i < NI4) ? __ldg(reinterpret_cast<const float4*>(item_emb) + i)
                         : __ldg(reinterpret_cast<const float4*>(user_emb) + (i - NI4));
    float4 B = reinterpret_cast<const float4*>(b)[i];
    float4 C = reinterpret_cast<const float4*>(c)[i];
    const float s = 1.f / 3.f;
    reinterpret_cast<float4*>(out)[i] =
        make_float4((A.x + B.x + C.x) * s, (A.y + B.y + C.y) * s,
                    (A.z + B.z + C.z) * s, (A.w + B.w + C.w) * s);
}

// ---------------- tf32 tensor-core projection + BN + lrelu + gate --------------
// Block = 256 thr (8 warps). Tile 128 rows x 64 cols. Warp w: rows w*16..w*16+15.
// smem X: [128 rows][64 k] tf32, pitch 68. smem Wt: [64 n][64 k] tf32, pitch 68 (transposed).
#define XPITCH 68
template <int F>
__global__ __launch_bounds__(256)
void projgate_kernel(const float* __restrict__ x, const float* __restrict__ W,
                     const float* __restrict__ b, const float* __restrict__ g,
                     const float* __restrict__ beta,
                     const float* __restrict__ Wg, const float* __restrict__ bg,
                     const float* __restrict__ item_emb,
                     float* __restrict__ out) {
    __shared__ uint32_t sX[128 * XPITCH];
    __shared__ uint32_t sWt[64 * XPITCH];

    const int tid  = threadIdx.x;
    const int warp = tid >> 5;
    const int lane = tid & 31;
    const int gq   = lane >> 2;     // groupID 0..7
    const int tg   = lane & 3;      // thread-in-group 0..3
    const int wr   = warp * 16;     // warp row base within tile
    const int r0   = blockIdx.x * 128;

    float acc[8][4];
#pragma unroll
    for (int nb = 0; nb < 8; nb++)
#pragma unroll
        for (int i = 0; i < 4; i++) acc[nb][i] = 0.f;

    for (int kc = 0; kc < F; kc += 64) {
        // ---- stage X chunk as tf32: thread -> row tid>>1, half tid&1 ----
        {
            int lr = tid >> 1, half = tid & 1;
            int gr = r0 + lr;
            uint32_t* dst = &sX[lr * XPITCH + half * 32];
            if (gr < NI) {
                const float4* src = reinterpret_cast<const float4*>(x + (size_t)gr * F + kc) + half * 8;
#pragma unroll
                for (int i = 0; i < 8; i++) {
                    float4 v = __ldg(src + i);
                    dst[i * 4 + 0] = f2tf32(v.x);
                    dst[i * 4 + 1] = f2tf32(v.y);
                    dst[i * 4 + 2] = f2tf32(v.z);
                    dst[i * 4 + 3] = f2tf32(v.w);
                }
            } else {
#pragma unroll
                for (int i = 0; i < 32; i++) dst[i] = 0u;
            }
        }
        // ---- stage W chunk transposed as tf32: thread -> k row tid>>2, 16 n ----
        {
            int wk = tid >> 2, ng = (tid & 3) * 16;
            const float4* src = reinterpret_cast<const float4*>(&W[(size_t)(kc + wk) * 64 + ng]);
#pragma unroll
            for (int i = 0; i < 4; i++) {
                float4 v = __ldg(src + i);
                int n = ng + i * 4;
                sWt[(n + 0) * XPITCH + wk] = f2tf32(v.x);
                sWt[(n + 1) * XPITCH + wk] = f2tf32(v.y);
                sWt[(n + 2) * XPITCH + wk] = f2tf32(v.z);
                sWt[(n + 3) * XPITCH + wk] = f2tf32(v.w);
            }
        }
        __syncthreads();

#pragma unroll
        for (int ks = 0; ks < 8; ks++) {
            int k4 = ks * 8;
            uint32_t a0 = sX[(wr + gq) * XPITCH + k4 + tg];
            uint32_t a1 = sX[(wr + gq + 8) * XPITCH + k4 + tg];
            uint32_t a2 = sX[(wr + gq) * XPITCH + k4 + tg + 4];
            uint32_t a3 = sX[(wr + gq + 8) * XPITCH + k4 + tg + 4];
#pragma unroll
            for (int nb = 0; nb < 8; nb++) {
                uint32_t b0 = sWt[(nb * 8 + gq) * XPITCH + k4 + tg];
                uint32_t b1 = sWt[(nb * 8 + gq) * XPITCH + k4 + tg + 4];
                mma_tf32(acc[nb][0], acc[nb][1], acc[nb][2], acc[nb][3],
                         a0, a1, a2, a3, b0, b1);
            }
        }
        __syncthreads();
    }

    // ---- BN + lrelu -> feat (tf32) back into sX; stage Wg transposed ----
    const float rs = rsqrtf(1.f + 1e-5f);
#pragma unroll
    for (int nb = 0; nb < 8; nb++) {
        int c0 = nb * 8 + 2 * tg;
        int c1 = c0 + 1;
        float s0 = __ldg(&g[c0]) * rs, s1 = __ldg(&g[c1]) * rs;
        float bb0 = __ldg(&b[c0]), bb1 = __ldg(&b[c1]);
        float be0 = __ldg(&beta[c0]), be1 = __ldg(&beta[c1]);
        float f00 = lrelu((acc[nb][0] + bb0) * s0 + be0);
        float f01 = lrelu((acc[nb][1] + bb1) * s1 + be1);
        float f10 = lrelu((acc[nb][2] + bb0) * s0 + be0);
        float f11 = lrelu((acc[nb][3] + bb1) * s1 + be1);
        sX[(wr + gq) * XPITCH + c0]     = f2tf32(f00);
        sX[(wr + gq) * XPITCH + c1]     = f2tf32(f01);
        sX[(wr + gq + 8) * XPITCH + c0] = f2tf32(f10);
        sX[(wr + gq + 8) * XPITCH + c1] = f2tf32(f11);
        acc[nb][0] = 0.f; acc[nb][1] = 0.f; acc[nb][2] = 0.f; acc[nb][3] = 0.f;
    }
    {
        int wk = tid >> 2, ng = (tid & 3) * 16;
        const float4* src = reinterpret_cast<const float4*>(&Wg[(size_t)wk * 64 + ng]);
#pragma unroll
        for (int i = 0; i < 4; i++) {
            float4 v = __ldg(src + i);
            int n = ng + i * 4;
            sWt[(n + 0) * XPITCH + wk] = f2tf32(v.x);
            sWt[(n + 1) * XPITCH + wk] = f2tf32(v.y);
            sWt[(n + 2) * XPITCH + wk] = f2tf32(v.z);
            sWt[(n + 3) * XPITCH + wk] = f2tf32(v.w);
        }
    }
    __syncthreads();

    // ---- gate GEMM: feat @ Wg ----
#pragma unroll
    for (int ks = 0; ks < 8; ks++) {
        int k4 = ks * 8;
        uint32_t a0 = sX[(wr + gq) * XPITCH + k4 + tg];
        uint32_t a1 = sX[(wr + gq + 8) * XPITCH + k4 + tg];
        uint32_t a2 = sX[(wr + gq) * XPITCH + k4 + tg + 4];
        uint32_t a3 = sX[(wr + gq + 8) * XPITCH + k4 + tg + 4];
#pragma unroll
        for (int nb = 0; nb < 8; nb++) {
            uint32_t b0 = sWt[(nb * 8 + gq) * XPITCH + k4 + tg];
            uint32_t b1 = sWt[(nb * 8 + gq) * XPITCH + k4 + tg + 4];
            mma_tf32(acc[nb][0], acc[nb][1], acc[nb][2], acc[nb][3],
                     a0, a1, a2, a3, b0, b1);
        }
    }

    // ---- sigmoid gate * item_emb -> out ----
    int rlo = r0 + wr + gq;
    int rhi = rlo + 8;
#pragma unroll
    for (int nb = 0; nb < 8; nb++) {
        int c0 = nb * 8 + 2 * tg;
        float bg0 = __ldg(&bg[c0]), bg1 = __ldg(&bg[c0 + 1]);
        if (rlo < NI) {
            float2 it = *reinterpret_cast<const float2*>(item_emb + (size_t)rlo * 64 + c0);
            float2 o;
            o.x = it.x / (1.f + __expf(-(acc[nb][0] + bg0)));
            o.y = it.y / (1.f + __expf(-(acc[nb][1] + bg1)));
            *reinterpret_cast<float2*>(out + (size_t)rlo * 64 + c0) = o;
        }
        if (rhi < NI) {
            float2 it = *reinterpret_cast<const float2*>(item_emb + (size_t)rhi * 64 + c0);
            float2 o;
            o.x = it.x / (1.f + __expf(-(acc[nb][2] + bg0)));
            o.y = it.y / (1.f + __expf(-(acc[nb][3] + bg1)));
            *reinterpret_cast<float2*>(out + (size_t)rhi * 64 + c0) = o;
        }
    }
}

// ---------------- attention fusion over a row range (writes out[1..3]) --------
__global__ __launch_bounds__(256, 2)
void att_kernel(const float* __restrict__ img_ui, const float* __restrict__ txt_ui,
                const float* __restrict__ W1, const float* __restrict__ b1,
                const float* __restrict__ w2, float* __restrict__ out,
                int r_begin, int r_end) {
    __shared__ float sei[4][64], set_[4][64];
    __shared__ float wsum[8][2];
    int d    = threadIdx.x & 63;
    int sub  = threadIdx.x >> 6;
    int warp = threadIdx.x >> 5;
    int lane = threadIdx.x & 31;

    float Wc[64];
#pragma unroll
    for (int k = 0; k < 64; k++) Wc[k] = __ldg(&W1[k * 64 + d]);
    float b1d = __ldg(&b1[d]);
    float w2d = __ldg(&w2[d]);

    int r0 = r_begin + blockIdx.x * 128;
#pragma unroll 1
    for (int i = 0; i < 32; i++) {
        int r = r0 + i * 4 + sub;
        bool valid = r < r_end;
        size_t base = (size_t)r * 64 + d;
        float ei = valid ? __ldg(&img_ui[base]) : 0.f;
        float et = valid ? __ldg(&txt_ui[base]) : 0.f;
        sei[sub][d]  = ei;
        set_[sub][d] = et;
        __syncthreads();

        float hi = b1d, ht = b1d;
#pragma unroll
        for (int k = 0; k < 64; k += 4) {
            float4 a = *reinterpret_cast<const float4*>(&sei[sub][k]);
            float4 b = *reinterpret_cast<const float4*>(&set_[sub][k]);
            hi += a.x * Wc[k] + a.y * Wc[k + 1] + a.z * Wc[k + 2] + a.w * Wc[k + 3];
            ht += b.x * Wc[k] + b.y * Wc[k + 1] + b.z * Wc[k + 2] + b.w * Wc[k + 3];
        }
        hi = lrelu(hi) * w2d;
        ht = lrelu(ht) * w2d;
#pragma unroll
        for (int o = 16; o; o >>= 1) {
            hi += __shfl_xor_sync(0xffffffffu, hi, o);
            ht += __shfl_xor_sync(0xffffffffu, ht, o);
        }
        if (lane == 0) { wsum[warp][0] = hi; wsum[warp][1] = ht; }
        __syncthreads();
        int wbase = sub * 2;
        float si = wsum[wbase][0] + wsum[wbase + 1][0];
        float st = wsum[wbase][1] + wsum[wbase + 1][1];
        float wimg = 1.f / (1.f + __expf(st - si));
        float common = wimg * ei + (1.f - wimg) * et;

        if (valid) {
            out[(size_t)1 * NN * DD + base] = ei - common;
            out[(size_t)2 * NN * DD + base] = et - common;
            out[(size_t)3 * NN * DD + base] = common;
        }
        __syncthreads();
    }
}

// ---------------- driver ------------------------------------------------------
static inline int g256(long long n) { return (int)((n + 255) / 256); }

extern "C" void kernel_launch(void* const* d_in, const int* in_sizes, int n_in,
                              void* d_out, int out_size) {
    const float* user_emb  = (const float*)d_in[0];
    const float* item_emb  = (const float*)d_in[1];
    const float* image_emb = (const float*)d_in[2];
    const float* text_emb  = (const float*)d_in[3];
    const float* W_img = (const float*)d_in[4];
    const float* b_img = (const float*)d_in[5];
    const float* bng_img = (const float*)d_in[6];
    const float* bnb_img = (const float*)d_in[7];
    const float* W_txt = (const float*)d_in[8];
    const float* b_txt = (const float*)d_in[9];
    const float* bng_txt = (const float*)d_in[10];
    const float* bnb_txt = (const float*)d_in[11];
    const float* W_gi = (const float*)d_in[12];
    const float* b_gi = (const float*)d_in[13];
    const float* W_gt = (const float*)d_in[14];
    const float* b_gt = (const float*)d_in[15];
    const float* W_c1 = (const float*)d_in[16];
    const float* b_c1 = (const float*)d_in[17];
    const float* w_c2 = (const float*)d_in[18];
    const float* ui_vals = (const float*)d_in[19];
    const float* R_vals  = (const float*)d_in[20];
    const float* ii_i_vals = (const float*)d_in[21];
    const float* ii_t_vals = (const float*)d_in[22];
    const int* ui_rows = (const int*)d_in[23];
    const int* ui_cols = (const int*)d_in[24];
    const int* R_rows  = (const int*)d_in[25];
    const int* R_cols  = (const int*)d_in[26];
    const int* ii_i_rows = (const int*)d_in[27];
    const int* ii_i_cols = (const int*)d_in[28];
    const int* ii_t_rows = (const int*)d_in[29];
    const int* ii_t_cols = (const int*)d_in[30];

    float* out = (float*)d_out;

    void* p;
    cudaGetSymbolAddress(&p, g_cat1);   float* cat1   = (float*)p;
    cudaGetSymbolAddress(&p, g_cat2);   float* cat2   = (float*)p;
    cudaGetSymbolAddress(&p, g_img_ui); float* img_ui = (float*)p;
    cudaGetSymbolAddress(&p, g_txt_ui); float* txt_ui = (float*)p;
    cudaGetSymbolAddress(&p, g_gi0);    float* gi0    = (float*)p;
    cudaGetSymbolAddress(&p, g_gi1);    float* gi1    = (float*)p;
    cudaGetSymbolAddress(&p, g_gt0);    float* gt0    = (float*)p;
    cudaGetSymbolAddress(&p, g_gt1);    float* gt1    = (float*)p;

    float* img_items = img_ui + (size_t)NU * DD;
    float* txt_items = txt_ui + (size_t)NU * DD;

    static cudaStream_t sA = nullptr, sB = nullptr, sC = nullptr;
    static cudaEvent_t eFork = nullptr, eA = nullptr, eB = nullptr, eC = nullptr;
    static cudaEvent_t eBh = nullptr, eCh = nullptr;
    if (!sA) {
        cudaStreamCreateWithFlags(&sA, cudaStreamNonBlocking);
        cudaStreamCreateWithFlags(&sB, cudaStreamNonBlocking);
        cudaStreamCreateWithFlags(&sC, cudaStreamNonBlocking);
        cudaEventCreateWithFlags(&eFork, cudaEventDisableTiming);
        cudaEventCreateWithFlags(&eA, cudaEventDisableTiming);
        cudaEventCreateWithFlags(&eB, cudaEventDisableTiming);
        cudaEventCreateWithFlags(&eC, cudaEventDisableTiming);
        cudaEventCreateWithFlags(&eBh, cudaEventDisableTiming);
        cudaEventCreateWithFlags(&eCh, cudaEventDisableTiming);
    }

    const int G_UI = NNZ_UI / 32;          // 31250
    const int G_II = NNZ_II / 32;          //  9375
    const int G_R  = NNZ_R * 16 / 256;     // 50000
    const size_t NNB = (size_t)NN * DD * sizeof(float);
    const size_t NIB = (size_t)NI * DD * sizeof(float);

    cudaEventRecord(eFork, 0);
    cudaStreamWaitEvent(sA, eFork, 0);
    cudaStreamWaitEvent(sB, eFork, 0);
    cudaStreamWaitEvent(sC, eFork, 0);

    // chain A: ui GCN -> out[0]
    cudaMemsetAsync(cat1, 0, NNB, sA);
    cudaMemsetAsync(cat2, 0, NNB, sA);
    spmm_cat_kernel<<<G_UI, 256, 0, sA>>>(ui_rows, ui_cols, ui_vals, item_emb, user_emb, cat1, NNZ_UI);
    spmm2_kernel<<<G_UI, 256, 0, sA>>>(ui_rows, ui_cols, ui_vals, cat1, cat2, NNZ_UI);
    mean3_cat_kernel<<<g256((long long)NN * 16), 256, 0, sA>>>(item_emb, user_emb, cat1, cat2, out);
    cudaEventRecord(eA, sA);

    // chain B: image branch up through ii-hop2
    cudaMemsetAsync(img_ui, 0, NNB, sB);
    cudaMemsetAsync(gi1, 0, NIB, sB);
    projgate_kernel<512><<<(NI + 127) / 128, 256, 0, sB>>>(image_emb, W_img, b_img, bng_img, bnb_img,
                                                           W_gi, b_gi, item_emb, gi0);
    spmm2_kernel<<<G_II, 256, 0, sB>>>(ii_i_rows, ii_i_cols, ii_i_vals, gi0, gi1, NNZ_II);
    spmm2_kernel<<<G_II, 256, 0, sB>>>(ii_i_rows, ii_i_cols, ii_i_vals, gi1, img_items, NNZ_II);
    cudaEventRecord(eBh, sB);

    // chain C: text branch up through ii-hop2
    cudaMemsetAsync(txt_ui, 0, NNB, sC);
    cudaMemsetAsync(gt1, 0, NIB, sC);
    projgate_kernel<384><<<(NI + 127) / 128, 256, 0, sC>>>(text_emb, W_txt, b_txt, bng_txt, bnb_txt,
                                                           W_gt, b_gt, item_emb, gt0);
    spmm2_kernel<<<G_II, 256, 0, sC>>>(ii_t_rows, ii_t_cols, ii_t_vals, gt0, gt1, NNZ_II);
    spmm2_kernel<<<G_II, 256, 0, sC>>>(ii_t_rows, ii_t_cols, ii_t_vals, gt1, txt_items, NNZ_II);
    cudaEventRecord(eCh, sC);

    // B: after both item halves ready, dualR (user rows) then att over user rows
    cudaStreamWaitEvent(sB, eCh, 0);
    spmm_dualR_kernel<<<G_R, 256, 0, sB>>>(R_rows, R_cols, R_vals, img_items, txt_items,
                                           img_ui, txt_ui, NNZ_R);
    att_kernel<<<(NU + 127) / 128, 256, 0, sB>>>(img_ui, txt_ui, W_c1, b_c1, w_c2, out, 0, NU);
    cudaEventRecord(eB, sB);

    // C: att over item rows runs concurrently with dualR
    cudaStreamWaitEvent(sC, eBh, 0);
    att_kernel<<<(NI + 127) / 128, 256, 0, sC>>>(img_ui, txt_ui, W_c1, b_c1, w_c2, out, NU, NN);
    cudaEventRecord(eC, sC);

    // join everything back to capture stream
    cudaStreamWaitEvent(0, eA, 0);
    cudaStreamWaitEvent(0, eB, 0);
    cudaStreamWaitEvent(0, eC, 0);
}